// round 1
// baseline (speedup 1.0000x reference)
#include <cuda_runtime.h>

// Problem constants
#define B_    16
#define T_    1024
#define C_    256
#define H_    8
#define D_    32
#define M_TOK (B_ * T_)      // 16384 tokens
#define FF_   (4 * C_)       // 1024
#define QKV_N (3 * C_)       // 768
#define ATT_SCALE 0.0625f    // C^-0.5 = 1/16
#define LN_EPS 1e-5f

// ---------------------------------------------------------------------------
// Scratch (device globals; allocation inside kernel_launch is forbidden)
// ---------------------------------------------------------------------------
__device__ float g_h   [M_TOK * C_];     // ln1 output
__device__ float g_wqkv[C_ * QKV_N];     // packed qkv weights (K=256, N=768) row-major
__device__ float g_qkv [M_TOK * QKV_N];  // q|k|v per token (cols 0..255 q, 256..511 k, 512..767 v)
__device__ float g_att [M_TOK * C_];     // attention output (head-concat layout)
__device__ float g_xmid[M_TOK * C_];     // x + attn proj
__device__ float g_h2  [M_TOK * C_];     // ln2 output
__device__ float g_ffn [M_TOK * FF_];    // relu(h2@w1+b1)

// ---------------------------------------------------------------------------
// Pack wq/wk/wv (H,C,D) into a single (C, 3C) row-major weight matrix
// col n: n<256 -> q head n/32 dim n%32 ; 256..511 -> k ; 512..767 -> v
// ---------------------------------------------------------------------------
__global__ void pack_wqkv_kernel(const float* __restrict__ wq,
                                 const float* __restrict__ wk,
                                 const float* __restrict__ wv,
                                 float* __restrict__ wqkv) {
    int i = blockIdx.x * blockDim.x + threadIdx.x;
    if (i >= C_ * QKV_N) return;
    int c = i / QKV_N;
    int n = i % QKV_N;
    const float* w = (n < C_) ? wq : ((n < 2 * C_) ? wk : wv);
    int nn = n & (C_ - 1);
    int h = nn >> 5;         // / 32
    int d = nn & 31;
    wqkv[i] = w[((size_t)h * C_ + c) * D_ + d];
}

// ---------------------------------------------------------------------------
// LayerNorm: one warp per 256-float row, 8 warps per block
// ---------------------------------------------------------------------------
__global__ __launch_bounds__(256) void layernorm_kernel(
    const float* __restrict__ in, const float* __restrict__ g,
    const float* __restrict__ b, float* __restrict__ out) {
    int warp = threadIdx.x >> 5;
    int lane = threadIdx.x & 31;
    int row  = blockIdx.x * 8 + warp;

    const float4* rp = (const float4*)(in + (size_t)row * C_);
    float4 v0 = rp[lane];
    float4 v1 = rp[lane + 32];

    float s  = v0.x + v0.y + v0.z + v0.w + v1.x + v1.y + v1.z + v1.w;
    float ss = v0.x * v0.x + v0.y * v0.y + v0.z * v0.z + v0.w * v0.w
             + v1.x * v1.x + v1.y * v1.y + v1.z * v1.z + v1.w * v1.w;
#pragma unroll
    for (int off = 16; off; off >>= 1) {
        s  += __shfl_xor_sync(0xffffffffu, s,  off);
        ss += __shfl_xor_sync(0xffffffffu, ss, off);
    }
    float mean = s * (1.0f / C_);
    float var  = ss * (1.0f / C_) - mean * mean;
    float inv  = rsqrtf(var + LN_EPS);

    const float4* gp = (const float4*)g;
    const float4* bp = (const float4*)b;
    float4 g0 = gp[lane], g1 = gp[lane + 32];
    float4 b0 = bp[lane], b1 = bp[lane + 32];

    float4 o0, o1;
    o0.x = (v0.x - mean) * inv * g0.x + b0.x;
    o0.y = (v0.y - mean) * inv * g0.y + b0.y;
    o0.z = (v0.z - mean) * inv * g0.z + b0.z;
    o0.w = (v0.w - mean) * inv * g0.w + b0.w;
    o1.x = (v1.x - mean) * inv * g1.x + b1.x;
    o1.y = (v1.y - mean) * inv * g1.y + b1.y;
    o1.z = (v1.z - mean) * inv * g1.z + b1.z;
    o1.w = (v1.w - mean) * inv * g1.w + b1.w;

    float4* op = (float4*)(out + (size_t)row * C_);
    op[lane]      = o0;
    op[lane + 32] = o1;
}

// ---------------------------------------------------------------------------
// SGEMM: C[M,N] = A[M,K] @ B[K,N] (+ epilogue)
// BM=BN=128, BK=8, 256 threads, 8x8 per thread.
// EPI: 0 = plain, 1 = +bias then relu, 2 = +bias +residual
// ---------------------------------------------------------------------------
template <int EPI>
__global__ __launch_bounds__(256) void sgemm_kernel(
    const float* __restrict__ A, const float* __restrict__ Bm,
    float* __restrict__ Cm, const float* __restrict__ bias,
    const float* __restrict__ res, int M, int N, int K) {
    __shared__ float As[8][128];
    __shared__ float Bs[8][128];

    const int tid  = threadIdx.x;
    const int brow = blockIdx.y * 128;
    const int bcol = blockIdx.x * 128;

    const int arow = tid >> 1;
    const int acol = (tid & 1) * 4;
    const int bkr  = tid >> 5;
    const int bcl  = (tid & 31) * 4;
    const int tr   = (tid >> 4) * 8;
    const int tc   = (tid & 15) * 8;

    float acc[8][8];
#pragma unroll
    for (int i = 0; i < 8; i++)
#pragma unroll
        for (int j = 0; j < 8; j++) acc[i][j] = 0.0f;

    const float* Aptr = A + (size_t)(brow + arow) * K + acol;
    const float* Bptr = Bm + (size_t)bkr * N + bcol + bcl;

    for (int k0 = 0; k0 < K; k0 += 8) {
        float4 a4 = *(const float4*)(Aptr + k0);
        float4 b4 = *(const float4*)(Bptr + (size_t)k0 * N);
        As[acol + 0][arow] = a4.x;
        As[acol + 1][arow] = a4.y;
        As[acol + 2][arow] = a4.z;
        As[acol + 3][arow] = a4.w;
        *(float4*)&Bs[bkr][bcl] = b4;
        __syncthreads();

#pragma unroll
        for (int k = 0; k < 8; k++) {
            float4 a0 = *(const float4*)&As[k][tr];
            float4 a1 = *(const float4*)&As[k][tr + 4];
            float4 b0 = *(const float4*)&Bs[k][tc];
            float4 b1 = *(const float4*)&Bs[k][tc + 4];
            float ra[8] = {a0.x, a0.y, a0.z, a0.w, a1.x, a1.y, a1.z, a1.w};
            float rb[8] = {b0.x, b0.y, b0.z, b0.w, b1.x, b1.y, b1.z, b1.w};
#pragma unroll
            for (int i = 0; i < 8; i++)
#pragma unroll
                for (int j = 0; j < 8; j++)
                    acc[i][j] = fmaf(ra[i], rb[j], acc[i][j]);
        }
        __syncthreads();
    }

    float bb[8];
#pragma unroll
    for (int j = 0; j < 8; j++)
        bb[j] = (EPI != 0) ? bias[bcol + tc + j] : 0.0f;

#pragma unroll
    for (int i = 0; i < 8; i++) {
        size_t roff = (size_t)(brow + tr + i) * N + bcol + tc;
#pragma unroll
        for (int j = 0; j < 8; j += 4) {
            float4 v;
            v.x = acc[i][j + 0] + bb[j + 0];
            v.y = acc[i][j + 1] + bb[j + 1];
            v.z = acc[i][j + 2] + bb[j + 2];
            v.w = acc[i][j + 3] + bb[j + 3];
            if (EPI == 1) {
                v.x = fmaxf(v.x, 0.0f);
                v.y = fmaxf(v.y, 0.0f);
                v.z = fmaxf(v.z, 0.0f);
                v.w = fmaxf(v.w, 0.0f);
            }
            if (EPI == 2) {
                float4 rr = *(const float4*)(res + roff + j);
                v.x += rr.x; v.y += rr.y; v.z += rr.z; v.w += rr.w;
            }
            *(float4*)(Cm + roff + j) = v;
        }
    }
}

// ---------------------------------------------------------------------------
// Causal flash attention, fp32.
// grid: (B*H, T/128), block: 128 threads, one thread per query row.
// q/o/scores in registers; K/V tiles of 32 keys in smem (float4 broadcasts).
// ---------------------------------------------------------------------------
__global__ __launch_bounds__(128) void attn_kernel(const float* __restrict__ qkv,
                                                   float* __restrict__ att) {
    const int bh = blockIdx.x;
    const int b  = bh >> 3;
    const int h  = bh & 7;
    const int r  = blockIdx.y * 128 + threadIdx.x;   // query position
    const size_t tokbase = (size_t)b * T_;

    const float4* q4p = (const float4*)(qkv + (tokbase + r) * QKV_N + h * D_);
    float q[D_];
#pragma unroll
    for (int d4 = 0; d4 < 8; d4++) {
        float4 t = q4p[d4];
        q[d4 * 4 + 0] = t.x * ATT_SCALE;
        q[d4 * 4 + 1] = t.y * ATT_SCALE;
        q[d4 * 4 + 2] = t.z * ATT_SCALE;
        q[d4 * 4 + 3] = t.w * ATT_SCALE;
    }

    float m = -1e30f, l = 0.0f;
    float o[D_];
#pragma unroll
    for (int d = 0; d < D_; d++) o[d] = 0.0f;

    __shared__ float4 Ks[32][8];
    __shared__ float4 Vs[32][8];

    const int smax = blockIdx.y * 128 + 127;
    for (int s0 = 0; s0 <= smax; s0 += 32) {
        // cooperative K/V tile load: 32 keys x 8 float4 = 256 float4 each
        {
            int e = threadIdx.x;
#pragma unroll
            for (int it = 0; it < 2; it++, e += 128) {
                int s  = e >> 3;
                int d4 = e & 7;
                const float* base = qkv + (tokbase + s0 + s) * QKV_N + h * D_;
                Ks[s][d4] = ((const float4*)(base + C_))[d4];
                Vs[s][d4] = ((const float4*)(base + 2 * C_))[d4];
            }
        }
        __syncthreads();

        if (s0 <= r) {
            float sc[32];
            float mt = -1e30f;
#pragma unroll
            for (int s = 0; s < 32; s++) {
                float acc = 0.0f;
#pragma unroll
                for (int d4 = 0; d4 < 8; d4++) {
                    float4 k4 = Ks[s][d4];
                    acc = fmaf(q[d4 * 4 + 0], k4.x, acc);
                    acc = fmaf(q[d4 * 4 + 1], k4.y, acc);
                    acc = fmaf(q[d4 * 4 + 2], k4.z, acc);
                    acc = fmaf(q[d4 * 4 + 3], k4.w, acc);
                }
                sc[s] = (s0 + s <= r) ? acc : -1e30f;
                mt = fmaxf(mt, sc[s]);
            }
            float mnew  = fmaxf(m, mt);
            float alpha = __expf(m - mnew);
            l *= alpha;
#pragma unroll
            for (int d = 0; d < D_; d++) o[d] *= alpha;
#pragma unroll
            for (int s = 0; s < 32; s++) {
                float p = __expf(sc[s] - mnew);
                l += p;
#pragma unroll
                for (int d4 = 0; d4 < 8; d4++) {
                    float4 v4 = Vs[s][d4];
                    o[d4 * 4 + 0] = fmaf(p, v4.x, o[d4 * 4 + 0]);
                    o[d4 * 4 + 1] = fmaf(p, v4.y, o[d4 * 4 + 1]);
                    o[d4 * 4 + 2] = fmaf(p, v4.z, o[d4 * 4 + 2]);
                    o[d4 * 4 + 3] = fmaf(p, v4.w, o[d4 * 4 + 3]);
                }
            }
            m = mnew;
        }
        __syncthreads();
    }

    float inv = 1.0f / l;
    float4* outp = (float4*)(att + (tokbase + r) * C_ + h * D_);
#pragma unroll
    for (int d4 = 0; d4 < 8; d4++)
        outp[d4] = make_float4(o[d4 * 4 + 0] * inv, o[d4 * 4 + 1] * inv,
                               o[d4 * 4 + 2] * inv, o[d4 * 4 + 3] * inv);
}

// ---------------------------------------------------------------------------
// Launch
// ---------------------------------------------------------------------------
extern "C" void kernel_launch(void* const* d_in, const int* in_sizes, int n_in,
                              void* d_out, int out_size) {
    const float* x      = (const float*)d_in[0];
    const float* wq     = (const float*)d_in[1];
    const float* wk     = (const float*)d_in[2];
    const float* wv     = (const float*)d_in[3];
    const float* w_proj = (const float*)d_in[4];
    const float* b_proj = (const float*)d_in[5];
    const float* w1     = (const float*)d_in[6];
    const float* b1     = (const float*)d_in[7];
    const float* w2     = (const float*)d_in[8];
    const float* b2     = (const float*)d_in[9];
    const float* ln1_g  = (const float*)d_in[10];
    const float* ln1_b  = (const float*)d_in[11];
    const float* ln2_g  = (const float*)d_in[12];
    const float* ln2_b  = (const float*)d_in[13];
    float* out = (float*)d_out;

    float *p_h, *p_wqkv, *p_qkv, *p_att, *p_xmid, *p_h2, *p_ffn;
    cudaGetSymbolAddress((void**)&p_h,    g_h);
    cudaGetSymbolAddress((void**)&p_wqkv, g_wqkv);
    cudaGetSymbolAddress((void**)&p_qkv,  g_qkv);
    cudaGetSymbolAddress((void**)&p_att,  g_att);
    cudaGetSymbolAddress((void**)&p_xmid, g_xmid);
    cudaGetSymbolAddress((void**)&p_h2,   g_h2);
    cudaGetSymbolAddress((void**)&p_ffn,  g_ffn);

    // 1. pack qkv weights into (256, 768)
    pack_wqkv_kernel<<<(C_ * QKV_N + 255) / 256, 256>>>(wq, wk, wv, p_wqkv);

    // 2. h = ln1(x)
    layernorm_kernel<<<M_TOK / 8, 256>>>(x, ln1_g, ln1_b, p_h);

    // 3. qkv = h @ Wqkv   (16384x256 @ 256x768)
    sgemm_kernel<0><<<dim3(QKV_N / 128, M_TOK / 128), 256>>>(
        p_h, p_wqkv, p_qkv, nullptr, nullptr, M_TOK, QKV_N, C_);

    // 4. causal attention -> head-concat layout
    attn_kernel<<<dim3(B_ * H_, T_ / 128), 128>>>(p_qkv, p_att);

    // 5. xmid = x + att @ w_proj + b_proj
    sgemm_kernel<2><<<dim3(C_ / 128, M_TOK / 128), 256>>>(
        p_att, w_proj, p_xmid, b_proj, x, M_TOK, C_, C_);

    // 6. h2 = ln2(xmid)
    layernorm_kernel<<<M_TOK / 8, 256>>>(p_xmid, ln2_g, ln2_b, p_h2);

    // 7. ffn = relu(h2 @ w1 + b1)
    sgemm_kernel<1><<<dim3(FF_ / 128, M_TOK / 128), 256>>>(
        p_h2, w1, p_ffn, b1, nullptr, M_TOK, FF_, C_);

    // 8. out = xmid + ffn @ w2 + b2
    sgemm_kernel<2><<<dim3(C_ / 128, M_TOK / 128), 256>>>(
        p_ffn, w2, out, b2, p_xmid, M_TOK, C_, FF_);
}

// round 3
// speedup vs baseline: 1.2816x; 1.2816x over previous
#include <cuda_runtime.h>
#include <cstdint>

// Problem constants
#define B_    16
#define T_    1024
#define C_    256
#define H_    8
#define D_    32
#define M_TOK (B_ * T_)      // 16384 tokens
#define FF_   (4 * C_)       // 1024
#define QKV_N (3 * C_)       // 768
#define ATT_SCALE 0.0625f
#define LN_EPS 1e-5f

// ---------------------------------------------------------------------------
// Scratch (device globals)
// ---------------------------------------------------------------------------
__device__ float g_h     [M_TOK * C_];
__device__ float g_qkv   [M_TOK * QKV_N];
__device__ float g_att   [M_TOK * C_];
__device__ float g_xmid  [M_TOK * C_];
__device__ float g_h2    [M_TOK * C_];
__device__ float g_ffn   [M_TOK * FF_];
__device__ float g_wqkvT [QKV_N * C_];   // [N=768][K=256]
__device__ float g_wprojT[C_ * C_];      // [N=256][K=256]
__device__ float g_w1T   [FF_ * C_];     // [N=1024][K=256]
__device__ float g_w2T   [C_ * FF_];     // [N=256][K=1024]

// ---------------------------------------------------------------------------
// Small helpers
// ---------------------------------------------------------------------------
__device__ __forceinline__ float tf32_rn(float x) {
    float y;
    asm("cvt.rna.tf32.f32 %0, %1;" : "=f"(y) : "f"(x));
    return y;
}
__device__ __forceinline__ void mma_tf32(float* d,
                                         const uint32_t* a, const uint32_t* b,
                                         const float* c) {
    asm volatile(
        "mma.sync.aligned.m16n8k8.row.col.f32.tf32.tf32.f32 "
        "{%0,%1,%2,%3}, {%4,%5,%6,%7}, {%8,%9}, {%10,%11,%12,%13};"
        : "=f"(d[0]), "=f"(d[1]), "=f"(d[2]), "=f"(d[3])
        : "r"(a[0]), "r"(a[1]), "r"(a[2]), "r"(a[3]),
          "r"(b[0]), "r"(b[1]),
          "f"(c[0]), "f"(c[1]), "f"(c[2]), "f"(c[3]));
}

// ---------------------------------------------------------------------------
// Weight pre-processing
// ---------------------------------------------------------------------------
__global__ void pack_wqkvT_kernel(const float* __restrict__ wq,
                                  const float* __restrict__ wk,
                                  const float* __restrict__ wv,
                                  float* __restrict__ wqkvT) {
    int i = blockIdx.x * blockDim.x + threadIdx.x;   // i = n*256 + c
    if (i >= QKV_N * C_) return;
    int n = i / C_;
    int c = i % C_;
    const float* w = (n < C_) ? wq : ((n < 2 * C_) ? wk : wv);
    int nn = n & (C_ - 1);
    int h = nn >> 5;
    int d = nn & 31;
    wqkvT[i] = w[((size_t)h * C_ + c) * D_ + d];
}

__global__ void transpose_kernel(const float* __restrict__ src,
                                 float* __restrict__ dst, int rows, int cols) {
    int i = blockIdx.x * blockDim.x + threadIdx.x;
    if (i >= rows * cols) return;
    int r = i / cols;
    int c = i % cols;
    dst[(size_t)c * rows + r] = src[i];
}

// ---------------------------------------------------------------------------
// LayerNorm: one warp per 256-float row
// ---------------------------------------------------------------------------
__global__ __launch_bounds__(256) void layernorm_kernel(
    const float* __restrict__ in, const float* __restrict__ g,
    const float* __restrict__ b, float* __restrict__ out) {
    int warp = threadIdx.x >> 5;
    int lane = threadIdx.x & 31;
    int row  = blockIdx.x * 8 + warp;

    const float4* rp = (const float4*)(in + (size_t)row * C_);
    float4 v0 = rp[lane];
    float4 v1 = rp[lane + 32];

    float s  = v0.x + v0.y + v0.z + v0.w + v1.x + v1.y + v1.z + v1.w;
    float ss = v0.x * v0.x + v0.y * v0.y + v0.z * v0.z + v0.w * v0.w
             + v1.x * v1.x + v1.y * v1.y + v1.z * v1.z + v1.w * v1.w;
#pragma unroll
    for (int off = 16; off; off >>= 1) {
        s  += __shfl_xor_sync(0xffffffffu, s,  off);
        ss += __shfl_xor_sync(0xffffffffu, ss, off);
    }
    float mean = s * (1.0f / C_);
    float var  = ss * (1.0f / C_) - mean * mean;
    float inv  = rsqrtf(var + LN_EPS);

    const float4* gp = (const float4*)g;
    const float4* bp = (const float4*)b;
    float4 g0 = gp[lane], g1 = gp[lane + 32];
    float4 b0 = bp[lane], b1 = bp[lane + 32];

    float4 o0, o1;
    o0.x = (v0.x - mean) * inv * g0.x + b0.x;
    o0.y = (v0.y - mean) * inv * g0.y + b0.y;
    o0.z = (v0.z - mean) * inv * g0.z + b0.z;
    o0.w = (v0.w - mean) * inv * g0.w + b0.w;
    o1.x = (v1.x - mean) * inv * g1.x + b1.x;
    o1.y = (v1.y - mean) * inv * g1.y + b1.y;
    o1.z = (v1.z - mean) * inv * g1.z + b1.z;
    o1.w = (v1.w - mean) * inv * g1.w + b1.w;

    float4* op = (float4*)(out + (size_t)row * C_);
    op[lane]      = o0;
    op[lane + 32] = o1;
}

// ---------------------------------------------------------------------------
// tf32 mma.sync GEMM: C[M,N] = A[M,K] @ Bt[N,K]^T (+ epilogue)
// CTA 128x128, BK=32, 256 threads = 8 warps in 4(m) x 2(n); warp tile 32x64.
// A/B chunks double-buffered through registers.
// EPI: 0 = plain, 1 = +bias+relu, 2 = +bias+residual
// ---------------------------------------------------------------------------
#define PADK 129   // smem row stride (floats) for k-major tiles

template <int EPI>
__global__ __launch_bounds__(256) void gemm_mma(
    const float* __restrict__ A, const float* __restrict__ Bt,
    float* __restrict__ Cm, const float* __restrict__ bias,
    const float* __restrict__ res, int M, int N, int K) {
    __shared__ float As[32][PADK];   // [k][m]
    __shared__ float Bs[32][PADK];   // [k][n]

    const int tid  = threadIdx.x;
    const int wid  = tid >> 5;
    const int lane = tid & 31;
    const int wm   = (wid & 3) * 32;        // warp row offset in CTA tile
    const int wn   = (wid >> 2) * 64;       // warp col offset in CTA tile
    const int gq   = lane >> 2;             // group id 0..7
    const int tq   = lane & 3;              // thread-in-group 0..3
    const int brow = blockIdx.y * 128;
    const int bcol = blockIdx.x * 128;

    float acc[2][8][4];
#pragma unroll
    for (int i = 0; i < 2; i++)
#pragma unroll
        for (int j = 0; j < 8; j++)
#pragma unroll
            for (int q = 0; q < 4; q++) acc[i][j][q] = 0.0f;

    // per-thread global load geometry: 1024 float4 per tile, 4 per thread
    const int lr  = tid >> 1;               // unused pattern replaced below
    (void)lr;

    float4 pa[4], pb[4];
    const float* Ag = A + (size_t)brow * K;
    const float* Bg = Bt + (size_t)bcol * K;

    // prologue load of chunk 0
#pragma unroll
    for (int i = 0; i < 4; i++) {
        int e = tid + i * 256;
        int r = e >> 3, c4 = e & 7;
        pa[i] = *(const float4*)(Ag + (size_t)r * K + c4 * 4);
        pb[i] = *(const float4*)(Bg + (size_t)r * K + c4 * 4);
    }

    const int KC = K >> 5;
    for (int kc = 0; kc < KC; kc++) {
        // store current chunk to smem with tf32 rounding
#pragma unroll
        for (int i = 0; i < 4; i++) {
            int e = tid + i * 256;
            int r = e >> 3, c4 = e & 7;
            As[c4 * 4 + 0][r] = tf32_rn(pa[i].x);
            As[c4 * 4 + 1][r] = tf32_rn(pa[i].y);
            As[c4 * 4 + 2][r] = tf32_rn(pa[i].z);
            As[c4 * 4 + 3][r] = tf32_rn(pa[i].w);
            Bs[c4 * 4 + 0][r] = tf32_rn(pb[i].x);
            Bs[c4 * 4 + 1][r] = tf32_rn(pb[i].y);
            Bs[c4 * 4 + 2][r] = tf32_rn(pb[i].z);
            Bs[c4 * 4 + 3][r] = tf32_rn(pb[i].w);
        }
        __syncthreads();

        // prefetch next chunk
        if (kc + 1 < KC) {
            const float* Agn = Ag + (kc + 1) * 32;
            const float* Bgn = Bg + (kc + 1) * 32;
#pragma unroll
            for (int i = 0; i < 4; i++) {
                int e = tid + i * 256;
                int r = e >> 3, c4 = e & 7;
                pa[i] = *(const float4*)(Agn + (size_t)r * K + c4 * 4);
                pb[i] = *(const float4*)(Bgn + (size_t)r * K + c4 * 4);
            }
        }

        // compute: 4 k-steps of 8
#pragma unroll
        for (int ks = 0; ks < 4; ks++) {
            const int k0 = ks * 8;
            uint32_t afr[2][4];
#pragma unroll
            for (int mt = 0; mt < 2; mt++) {
                int m0 = wm + mt * 16;
                afr[mt][0] = __float_as_uint(As[k0 + tq    ][m0 + gq    ]);
                afr[mt][1] = __float_as_uint(As[k0 + tq    ][m0 + gq + 8]);
                afr[mt][2] = __float_as_uint(As[k0 + tq + 4][m0 + gq    ]);
                afr[mt][3] = __float_as_uint(As[k0 + tq + 4][m0 + gq + 8]);
            }
            uint32_t bfr[8][2];
#pragma unroll
            for (int nt = 0; nt < 8; nt++) {
                int n0 = wn + nt * 8;
                bfr[nt][0] = __float_as_uint(Bs[k0 + tq    ][n0 + gq]);
                bfr[nt][1] = __float_as_uint(Bs[k0 + tq + 4][n0 + gq]);
            }
#pragma unroll
            for (int mt = 0; mt < 2; mt++)
#pragma unroll
                for (int nt = 0; nt < 8; nt++)
                    mma_tf32(acc[mt][nt], afr[mt], bfr[nt], acc[mt][nt]);
        }
        __syncthreads();
    }

    // epilogue
#pragma unroll
    for (int mt = 0; mt < 2; mt++) {
        int row0 = brow + wm + mt * 16 + gq;
#pragma unroll
        for (int half = 0; half < 2; half++) {       // c0c1 (row0) / c2c3 (row0+8)
            int row = row0 + half * 8;
            float* outr = Cm + (size_t)row * N;
            const float* resr = (EPI == 2) ? (res + (size_t)row * N) : nullptr;
#pragma unroll
            for (int nt = 0; nt < 8; nt++) {
                int col = bcol + wn + nt * 8 + tq * 2;
                float2 v;
                v.x = acc[mt][nt][half * 2 + 0];
                v.y = acc[mt][nt][half * 2 + 1];
                if (EPI != 0) {
                    v.x += bias[col + 0];
                    v.y += bias[col + 1];
                }
                if (EPI == 1) {
                    v.x = fmaxf(v.x, 0.0f);
                    v.y = fmaxf(v.y, 0.0f);
                }
                if (EPI == 2) {
                    float2 rr = *(const float2*)(resr + col);
                    v.x += rr.x;
                    v.y += rr.y;
                }
                *(float2*)(outr + col) = v;
            }
        }
    }
}

// ---------------------------------------------------------------------------
// Causal flash attention, fp32 (unchanged)
// ---------------------------------------------------------------------------
__global__ __launch_bounds__(128) void attn_kernel(const float* __restrict__ qkv,
                                                   float* __restrict__ att) {
    const int bh = blockIdx.x;
    const int b  = bh >> 3;
    const int h  = bh & 7;
    const int r  = blockIdx.y * 128 + threadIdx.x;
    const size_t tokbase = (size_t)b * T_;

    const float4* q4p = (const float4*)(qkv + (tokbase + r) * QKV_N + h * D_);
    float q[D_];
#pragma unroll
    for (int d4 = 0; d4 < 8; d4++) {
        float4 t = q4p[d4];
        q[d4 * 4 + 0] = t.x * ATT_SCALE;
        q[d4 * 4 + 1] = t.y * ATT_SCALE;
        q[d4 * 4 + 2] = t.z * ATT_SCALE;
        q[d4 * 4 + 3] = t.w * ATT_SCALE;
    }

    float m = -1e30f, l = 0.0f;
    float o[D_];
#pragma unroll
    for (int d = 0; d < D_; d++) o[d] = 0.0f;

    __shared__ float4 Ks[32][8];
    __shared__ float4 Vs[32][8];

    const int smax = blockIdx.y * 128 + 127;
    for (int s0 = 0; s0 <= smax; s0 += 32) {
        {
            int e = threadIdx.x;
#pragma unroll
            for (int it = 0; it < 2; it++, e += 128) {
                int s  = e >> 3;
                int d4 = e & 7;
                const float* base = qkv + (tokbase + s0 + s) * QKV_N + h * D_;
                Ks[s][d4] = ((const float4*)(base + C_))[d4];
                Vs[s][d4] = ((const float4*)(base + 2 * C_))[d4];
            }
        }
        __syncthreads();

        if (s0 <= r) {
            float sc[32];
            float mt = -1e30f;
#pragma unroll
            for (int s = 0; s < 32; s++) {
                float acc = 0.0f;
#pragma unroll
                for (int d4 = 0; d4 < 8; d4++) {
                    float4 k4 = Ks[s][d4];
                    acc = fmaf(q[d4 * 4 + 0], k4.x, acc);
                    acc = fmaf(q[d4 * 4 + 1], k4.y, acc);
                    acc = fmaf(q[d4 * 4 + 2], k4.z, acc);
                    acc = fmaf(q[d4 * 4 + 3], k4.w, acc);
                }
                sc[s] = (s0 + s <= r) ? acc : -1e30f;
                mt = fmaxf(mt, sc[s]);
            }
            float mnew  = fmaxf(m, mt);
            float alpha = __expf(m - mnew);
            l *= alpha;
#pragma unroll
            for (int d = 0; d < D_; d++) o[d] *= alpha;
#pragma unroll
            for (int s = 0; s < 32; s++) {
                float p = __expf(sc[s] - mnew);
                l += p;
#pragma unroll
                for (int d4 = 0; d4 < 8; d4++) {
                    float4 v4 = Vs[s][d4];
                    o[d4 * 4 + 0] = fmaf(p, v4.x, o[d4 * 4 + 0]);
                    o[d4 * 4 + 1] = fmaf(p, v4.y, o[d4 * 4 + 1]);
                    o[d4 * 4 + 2] = fmaf(p, v4.z, o[d4 * 4 + 2]);
                    o[d4 * 4 + 3] = fmaf(p, v4.w, o[d4 * 4 + 3]);
                }
            }
            m = mnew;
        }
        __syncthreads();
    }

    float inv = 1.0f / l;
    float4* outp = (float4*)(att + (tokbase + r) * C_ + h * D_);
#pragma unroll
    for (int d4 = 0; d4 < 8; d4++)
        outp[d4] = make_float4(o[d4 * 4 + 0] * inv, o[d4 * 4 + 1] * inv,
                               o[d4 * 4 + 2] * inv, o[d4 * 4 + 3] * inv);
}

// ---------------------------------------------------------------------------
// Launch
// ---------------------------------------------------------------------------
extern "C" void kernel_launch(void* const* d_in, const int* in_sizes, int n_in,
                              void* d_out, int out_size) {
    const float* x      = (const float*)d_in[0];
    const float* wq     = (const float*)d_in[1];
    const float* wk     = (const float*)d_in[2];
    const float* wv     = (const float*)d_in[3];
    const float* w_proj = (const float*)d_in[4];
    const float* b_proj = (const float*)d_in[5];
    const float* w1     = (const float*)d_in[6];
    const float* b1     = (const float*)d_in[7];
    const float* w2     = (const float*)d_in[8];
    const float* b2     = (const float*)d_in[9];
    const float* ln1_g  = (const float*)d_in[10];
    const float* ln1_b  = (const float*)d_in[11];
    const float* ln2_g  = (const float*)d_in[12];
    const float* ln2_b  = (const float*)d_in[13];
    float* out = (float*)d_out;

    float *p_h, *p_qkv, *p_att, *p_xmid, *p_h2, *p_ffn;
    float *p_wqkvT, *p_wprojT, *p_w1T, *p_w2T;
    cudaGetSymbolAddress((void**)&p_h,      g_h);
    cudaGetSymbolAddress((void**)&p_qkv,    g_qkv);
    cudaGetSymbolAddress((void**)&p_att,    g_att);
    cudaGetSymbolAddress((void**)&p_xmid,   g_xmid);
    cudaGetSymbolAddress((void**)&p_h2,     g_h2);
    cudaGetSymbolAddress((void**)&p_ffn,    g_ffn);
    cudaGetSymbolAddress((void**)&p_wqkvT,  g_wqkvT);
    cudaGetSymbolAddress((void**)&p_wprojT, g_wprojT);
    cudaGetSymbolAddress((void**)&p_w1T,    g_w1T);
    cudaGetSymbolAddress((void**)&p_w2T,    g_w2T);

    // weight prep
    pack_wqkvT_kernel<<<(QKV_N * C_ + 255) / 256, 256>>>(wq, wk, wv, p_wqkvT);
    transpose_kernel<<<(C_ * C_ + 255) / 256, 256>>>(w_proj, p_wprojT, C_, C_);
    transpose_kernel<<<(C_ * FF_ + 255) / 256, 256>>>(w1, p_w1T, C_, FF_);
    transpose_kernel<<<(FF_ * C_ + 255) / 256, 256>>>(w2, p_w2T, FF_, C_);

    // 1. h = ln1(x)
    layernorm_kernel<<<M_TOK / 8, 256>>>(x, ln1_g, ln1_b, p_h);

    // 2. qkv = h @ Wqkv
    gemm_mma<0><<<dim3(QKV_N / 128, M_TOK / 128), 256>>>(
        p_h, p_wqkvT, p_qkv, nullptr, nullptr, M_TOK, QKV_N, C_);

    // 3. causal attention
    attn_kernel<<<dim3(B_ * H_, T_ / 128), 128>>>(p_qkv, p_att);

    // 4. xmid = x + att @ w_proj + b_proj
    gemm_mma<2><<<dim3(C_ / 128, M_TOK / 128), 256>>>(
        p_att, p_wprojT, p_xmid, b_proj, x, M_TOK, C_, C_);

    // 5. h2 = ln2(xmid)
    layernorm_kernel<<<M_TOK / 8, 256>>>(p_xmid, ln2_g, ln2_b, p_h2);

    // 6. ffn = relu(h2 @ w1 + b1)
    gemm_mma<1><<<dim3(FF_ / 128, M_TOK / 128), 256>>>(
        p_h2, p_w1T, p_ffn, b1, nullptr, M_TOK, FF_, C_);

    // 7. out = xmid + ffn @ w2 + b2
    gemm_mma<2><<<dim3(C_ / 128, M_TOK / 128), 256>>>(
        p_ffn, p_w2T, out, b2, p_xmid, M_TOK, C_, FF_);
}

// round 5
// speedup vs baseline: 1.7962x; 1.4016x over previous
#include <cuda_runtime.h>
#include <cstdint>

// Problem constants
#define B_    16
#define T_    1024
#define C_    256
#define H_    8
#define D_    32
#define M_TOK (B_ * T_)      // 16384 tokens
#define FF_   (4 * C_)       // 1024
#define QKV_N (3 * C_)       // 768
#define ATT_SCALE 0.0625f
#define LN_EPS 1e-5f

// ---------------------------------------------------------------------------
// Scratch (device globals)
// ---------------------------------------------------------------------------
__device__ float g_h     [M_TOK * C_];
__device__ float g_qkv   [M_TOK * QKV_N];
__device__ float g_att   [M_TOK * C_];
__device__ float g_xmid  [M_TOK * C_];
__device__ float g_h2    [M_TOK * C_];
__device__ float g_ffn   [M_TOK * FF_];
__device__ float g_wqkvT [QKV_N * C_];   // [N=768][K=256]
__device__ float g_wprojT[C_ * C_];      // [N=256][K=256]
__device__ float g_w1T   [FF_ * C_];     // [N=1024][K=256]
__device__ float g_w2T   [C_ * FF_];     // [N=256][K=1024]

// ---------------------------------------------------------------------------
// Small helpers
// ---------------------------------------------------------------------------
__device__ __forceinline__ float tf32_rn(float x) {
    float y;
    asm("cvt.rna.tf32.f32 %0, %1;" : "=f"(y) : "f"(x));
    return y;
}
__device__ __forceinline__ void mma_tf32(float* d,
                                         const uint32_t* a, const uint32_t* b,
                                         const float* c) {
    asm volatile(
        "mma.sync.aligned.m16n8k8.row.col.f32.tf32.tf32.f32 "
        "{%0,%1,%2,%3}, {%4,%5,%6,%7}, {%8,%9}, {%10,%11,%12,%13};"
        : "=f"(d[0]), "=f"(d[1]), "=f"(d[2]), "=f"(d[3])
        : "r"(a[0]), "r"(a[1]), "r"(a[2]), "r"(a[3]),
          "r"(b[0]), "r"(b[1]),
          "f"(c[0]), "f"(c[1]), "f"(c[2]), "f"(c[3]));
}

// ---------------------------------------------------------------------------
// Weight pre-processing
// ---------------------------------------------------------------------------
__global__ void pack_wqkvT_kernel(const float* __restrict__ wq,
                                  const float* __restrict__ wk,
                                  const float* __restrict__ wv,
                                  float* __restrict__ wqkvT) {
    int i = blockIdx.x * blockDim.x + threadIdx.x;   // i = n*256 + c
    if (i >= QKV_N * C_) return;
    int n = i / C_;
    int c = i % C_;
    const float* w = (n < C_) ? wq : ((n < 2 * C_) ? wk : wv);
    int nn = n & (C_ - 1);
    int h = nn >> 5;
    int d = nn & 31;
    wqkvT[i] = w[((size_t)h * C_ + c) * D_ + d];
}

__global__ void transpose_kernel(const float* __restrict__ src,
                                 float* __restrict__ dst, int rows, int cols) {
    int i = blockIdx.x * blockDim.x + threadIdx.x;
    if (i >= rows * cols) return;
    int r = i / cols;
    int c = i % cols;
    dst[(size_t)c * rows + r] = src[i];
}

// ---------------------------------------------------------------------------
// LayerNorm: one warp per 256-float row
// ---------------------------------------------------------------------------
__global__ __launch_bounds__(256) void layernorm_kernel(
    const float* __restrict__ in, const float* __restrict__ g,
    const float* __restrict__ b, float* __restrict__ out) {
    int warp = threadIdx.x >> 5;
    int lane = threadIdx.x & 31;
    int row  = blockIdx.x * 8 + warp;

    const float4* rp = (const float4*)(in + (size_t)row * C_);
    float4 v0 = rp[lane];
    float4 v1 = rp[lane + 32];

    float s  = v0.x + v0.y + v0.z + v0.w + v1.x + v1.y + v1.z + v1.w;
    float ss = v0.x * v0.x + v0.y * v0.y + v0.z * v0.z + v0.w * v0.w
             + v1.x * v1.x + v1.y * v1.y + v1.z * v1.z + v1.w * v1.w;
#pragma unroll
    for (int off = 16; off; off >>= 1) {
        s  += __shfl_xor_sync(0xffffffffu, s,  off);
        ss += __shfl_xor_sync(0xffffffffu, ss, off);
    }
    float mean = s * (1.0f / C_);
    float var  = ss * (1.0f / C_) - mean * mean;
    float inv  = rsqrtf(var + LN_EPS);

    const float4* gp = (const float4*)g;
    const float4* bp = (const float4*)b;
    float4 g0 = gp[lane], g1 = gp[lane + 32];
    float4 b0 = bp[lane], b1 = bp[lane + 32];

    float4 o0, o1;
    o0.x = (v0.x - mean) * inv * g0.x + b0.x;
    o0.y = (v0.y - mean) * inv * g0.y + b0.y;
    o0.z = (v0.z - mean) * inv * g0.z + b0.z;
    o0.w = (v0.w - mean) * inv * g0.w + b0.w;
    o1.x = (v1.x - mean) * inv * g1.x + b1.x;
    o1.y = (v1.y - mean) * inv * g1.y + b1.y;
    o1.z = (v1.z - mean) * inv * g1.z + b1.z;
    o1.w = (v1.w - mean) * inv * g1.w + b1.w;

    float4* op = (float4*)(out + (size_t)row * C_);
    op[lane]      = o0;
    op[lane + 32] = o1;
}

// ---------------------------------------------------------------------------
// tf32 mma.sync GEMM (unchanged): C = A @ Bt^T (+ epilogue)
// ---------------------------------------------------------------------------
#define PADK 129

template <int EPI>
__global__ __launch_bounds__(256) void gemm_mma(
    const float* __restrict__ A, const float* __restrict__ Bt,
    float* __restrict__ Cm, const float* __restrict__ bias,
    const float* __restrict__ res, int M, int N, int K) {
    __shared__ float As[32][PADK];
    __shared__ float Bs[32][PADK];

    const int tid  = threadIdx.x;
    const int wid  = tid >> 5;
    const int lane = tid & 31;
    const int wm   = (wid & 3) * 32;
    const int wn   = (wid >> 2) * 64;
    const int gq   = lane >> 2;
    const int tq   = lane & 3;
    const int brow = blockIdx.y * 128;
    const int bcol = blockIdx.x * 128;

    float acc[2][8][4];
#pragma unroll
    for (int i = 0; i < 2; i++)
#pragma unroll
        for (int j = 0; j < 8; j++)
#pragma unroll
            for (int q = 0; q < 4; q++) acc[i][j][q] = 0.0f;

    float4 pa[4], pb[4];
    const float* Ag = A + (size_t)brow * K;
    const float* Bg = Bt + (size_t)bcol * K;

#pragma unroll
    for (int i = 0; i < 4; i++) {
        int e = tid + i * 256;
        int r = e >> 3, c4 = e & 7;
        pa[i] = *(const float4*)(Ag + (size_t)r * K + c4 * 4);
        pb[i] = *(const float4*)(Bg + (size_t)r * K + c4 * 4);
    }

    const int KC = K >> 5;
    for (int kc = 0; kc < KC; kc++) {
#pragma unroll
        for (int i = 0; i < 4; i++) {
            int e = tid + i * 256;
            int r = e >> 3, c4 = e & 7;
            As[c4 * 4 + 0][r] = tf32_rn(pa[i].x);
            As[c4 * 4 + 1][r] = tf32_rn(pa[i].y);
            As[c4 * 4 + 2][r] = tf32_rn(pa[i].z);
            As[c4 * 4 + 3][r] = tf32_rn(pa[i].w);
            Bs[c4 * 4 + 0][r] = tf32_rn(pb[i].x);
            Bs[c4 * 4 + 1][r] = tf32_rn(pb[i].y);
            Bs[c4 * 4 + 2][r] = tf32_rn(pb[i].z);
            Bs[c4 * 4 + 3][r] = tf32_rn(pb[i].w);
        }
        __syncthreads();

        if (kc + 1 < KC) {
            const float* Agn = Ag + (kc + 1) * 32;
            const float* Bgn = Bg + (kc + 1) * 32;
#pragma unroll
            for (int i = 0; i < 4; i++) {
                int e = tid + i * 256;
                int r = e >> 3, c4 = e & 7;
                pa[i] = *(const float4*)(Agn + (size_t)r * K + c4 * 4);
                pb[i] = *(const float4*)(Bgn + (size_t)r * K + c4 * 4);
            }
        }

#pragma unroll
        for (int ks = 0; ks < 4; ks++) {
            const int k0 = ks * 8;
            uint32_t afr[2][4];
#pragma unroll
            for (int mt = 0; mt < 2; mt++) {
                int m0 = wm + mt * 16;
                afr[mt][0] = __float_as_uint(As[k0 + tq    ][m0 + gq    ]);
                afr[mt][1] = __float_as_uint(As[k0 + tq    ][m0 + gq + 8]);
                afr[mt][2] = __float_as_uint(As[k0 + tq + 4][m0 + gq    ]);
                afr[mt][3] = __float_as_uint(As[k0 + tq + 4][m0 + gq + 8]);
            }
            uint32_t bfr[8][2];
#pragma unroll
            for (int nt = 0; nt < 8; nt++) {
                int n0 = wn + nt * 8;
                bfr[nt][0] = __float_as_uint(Bs[k0 + tq    ][n0 + gq]);
                bfr[nt][1] = __float_as_uint(Bs[k0 + tq + 4][n0 + gq]);
            }
#pragma unroll
            for (int mt = 0; mt < 2; mt++)
#pragma unroll
                for (int nt = 0; nt < 8; nt++)
                    mma_tf32(acc[mt][nt], afr[mt], bfr[nt], acc[mt][nt]);
        }
        __syncthreads();
    }

#pragma unroll
    for (int mt = 0; mt < 2; mt++) {
        int row0 = brow + wm + mt * 16 + gq;
#pragma unroll
        for (int half = 0; half < 2; half++) {
            int row = row0 + half * 8;
            float* outr = Cm + (size_t)row * N;
            const float* resr = (EPI == 2) ? (res + (size_t)row * N) : nullptr;
#pragma unroll
            for (int nt = 0; nt < 8; nt++) {
                int col = bcol + wn + nt * 8 + tq * 2;
                float2 v;
                v.x = acc[mt][nt][half * 2 + 0];
                v.y = acc[mt][nt][half * 2 + 1];
                if (EPI != 0) {
                    v.x += bias[col + 0];
                    v.y += bias[col + 1];
                }
                if (EPI == 1) {
                    v.x = fmaxf(v.x, 0.0f);
                    v.y = fmaxf(v.y, 0.0f);
                }
                if (EPI == 2) {
                    float2 rr = *(const float2*)(resr + col);
                    v.x += rr.x;
                    v.y += rr.y;
                }
                *(float2*)(outr + col) = v;
            }
        }
    }
}

// ---------------------------------------------------------------------------
// Tensor-core causal flash attention (tf32 mma.sync).
// grid (B*H, T/64), 128 threads = 4 warps; warp = 16 query rows.
// Key tiles of 64; K/V tiles padded to 40; P tile padded to 72 (64 cols!).
// ---------------------------------------------------------------------------
#define AT_PAD  40
#define AT_PPAD 72

__global__ __launch_bounds__(128) void attn_tc_kernel(
    const float* __restrict__ qkv, float* __restrict__ att) {
    __shared__ float Qs[64][33];
    __shared__ float Ks[64][AT_PAD];
    __shared__ float Vs[64][AT_PAD];
    __shared__ float Ps[4][16][AT_PPAD];

    const int bh = blockIdx.x;
    const int b  = bh >> 3;
    const int h  = bh & 7;
    const int qt = blockIdx.y;
    const int tid  = threadIdx.x;
    const int wid  = tid >> 5;
    const int lane = tid & 31;
    const int gq   = lane >> 2;
    const int tq   = lane & 3;
    const size_t tokbase = (size_t)b * T_;
    const int qrow0 = qt * 64;
    const int m0 = wid * 16;

    // --- load + scale + round Q tile (64x32) ---
#pragma unroll
    for (int i = 0; i < 4; i++) {
        int e = tid + i * 128;
        int r = e >> 3, c4 = e & 7;
        float4 v = *(const float4*)(qkv + (tokbase + qrow0 + r) * QKV_N + h * D_ + c4 * 4);
        Qs[r][c4 * 4 + 0] = tf32_rn(v.x * ATT_SCALE);
        Qs[r][c4 * 4 + 1] = tf32_rn(v.y * ATT_SCALE);
        Qs[r][c4 * 4 + 2] = tf32_rn(v.z * ATT_SCALE);
        Qs[r][c4 * 4 + 3] = tf32_rn(v.w * ATT_SCALE);
    }
    __syncthreads();

    uint32_t qf[4][4];
#pragma unroll
    for (int ks = 0; ks < 4; ks++) {
        qf[ks][0] = __float_as_uint(Qs[m0 + gq    ][8 * ks + tq    ]);
        qf[ks][1] = __float_as_uint(Qs[m0 + gq + 8][8 * ks + tq    ]);
        qf[ks][2] = __float_as_uint(Qs[m0 + gq    ][8 * ks + tq + 4]);
        qf[ks][3] = __float_as_uint(Qs[m0 + gq + 8][8 * ks + tq + 4]);
    }

    const int r0 = qrow0 + m0 + gq;     // row for c0/c1
    const int r1 = r0 + 8;              // row for c2/c3

    float mrow0 = -1e30f, mrow1 = -1e30f;
    float l0 = 0.0f, l1 = 0.0f;
    float o[4][4];
#pragma unroll
    for (int i = 0; i < 4; i++)
#pragma unroll
        for (int j = 0; j < 4; j++) o[i][j] = 0.0f;

    for (int s0 = 0; s0 <= qrow0; s0 += 64) {
        __syncthreads();   // previous-iteration Ks/Vs readers done
#pragma unroll
        for (int i = 0; i < 4; i++) {
            int e = tid + i * 128;
            int r = e >> 3, c4 = e & 7;
            const float* base = qkv + (tokbase + s0 + r) * QKV_N + h * D_ + c4 * 4;
            float4 kv = *(const float4*)(base + C_);
            float4 vv = *(const float4*)(base + 2 * C_);
            Ks[r][c4 * 4 + 0] = tf32_rn(kv.x);
            Ks[r][c4 * 4 + 1] = tf32_rn(kv.y);
            Ks[r][c4 * 4 + 2] = tf32_rn(kv.z);
            Ks[r][c4 * 4 + 3] = tf32_rn(kv.w);
            Vs[r][c4 * 4 + 0] = tf32_rn(vv.x);
            Vs[r][c4 * 4 + 1] = tf32_rn(vv.y);
            Vs[r][c4 * 4 + 2] = tf32_rn(vv.z);
            Vs[r][c4 * 4 + 3] = tf32_rn(vv.w);
        }
        __syncthreads();

        // --- S = Q @ K^T  (16 x 64 per warp) ---
        float S[8][4];
#pragma unroll
        for (int nt = 0; nt < 8; nt++) {
            S[nt][0] = S[nt][1] = S[nt][2] = S[nt][3] = 0.0f;
#pragma unroll
            for (int ks = 0; ks < 4; ks++) {
                uint32_t bfr[2];
                bfr[0] = __float_as_uint(Ks[nt * 8 + gq][8 * ks + tq    ]);
                bfr[1] = __float_as_uint(Ks[nt * 8 + gq][8 * ks + tq + 4]);
                mma_tf32(S[nt], qf[ks], bfr, S[nt]);
            }
        }

        // --- causal mask (diagonal tile only) ---
        if (s0 == qrow0) {
#pragma unroll
            for (int nt = 0; nt < 8; nt++) {
                int col = s0 + nt * 8 + 2 * tq;
                if (col     > r0) S[nt][0] = -1e30f;
                if (col + 1 > r0) S[nt][1] = -1e30f;
                if (col     > r1) S[nt][2] = -1e30f;
                if (col + 1 > r1) S[nt][3] = -1e30f;
            }
        }

        // --- online softmax ---
        float mx0 = -1e30f, mx1 = -1e30f;
#pragma unroll
        for (int nt = 0; nt < 8; nt++) {
            mx0 = fmaxf(mx0, fmaxf(S[nt][0], S[nt][1]));
            mx1 = fmaxf(mx1, fmaxf(S[nt][2], S[nt][3]));
        }
        mx0 = fmaxf(mx0, __shfl_xor_sync(0xffffffffu, mx0, 1));
        mx0 = fmaxf(mx0, __shfl_xor_sync(0xffffffffu, mx0, 2));
        mx1 = fmaxf(mx1, __shfl_xor_sync(0xffffffffu, mx1, 1));
        mx1 = fmaxf(mx1, __shfl_xor_sync(0xffffffffu, mx1, 2));

        float mn0 = fmaxf(mrow0, mx0);
        float mn1 = fmaxf(mrow1, mx1);
        float a0 = __expf(mrow0 - mn0);
        float a1 = __expf(mrow1 - mn1);
        mrow0 = mn0;
        mrow1 = mn1;

        float sum0 = 0.0f, sum1 = 0.0f;
#pragma unroll
        for (int nt = 0; nt < 8; nt++) {
            S[nt][0] = __expf(S[nt][0] - mn0);
            S[nt][1] = __expf(S[nt][1] - mn0);
            S[nt][2] = __expf(S[nt][2] - mn1);
            S[nt][3] = __expf(S[nt][3] - mn1);
            sum0 += S[nt][0] + S[nt][1];
            sum1 += S[nt][2] + S[nt][3];
        }
        sum0 += __shfl_xor_sync(0xffffffffu, sum0, 1);
        sum0 += __shfl_xor_sync(0xffffffffu, sum0, 2);
        sum1 += __shfl_xor_sync(0xffffffffu, sum1, 1);
        sum1 += __shfl_xor_sync(0xffffffffu, sum1, 2);
        l0 = l0 * a0 + sum0;
        l1 = l1 * a1 + sum1;

#pragma unroll
        for (int d4 = 0; d4 < 4; d4++) {
            o[d4][0] *= a0;
            o[d4][1] *= a0;
            o[d4][2] *= a1;
            o[d4][3] *= a1;
        }

        // --- stage P (tf32) to per-warp smem ---
#pragma unroll
        for (int nt = 0; nt < 8; nt++) {
            float2 p0 = make_float2(tf32_rn(S[nt][0]), tf32_rn(S[nt][1]));
            float2 p1 = make_float2(tf32_rn(S[nt][2]), tf32_rn(S[nt][3]));
            *(float2*)&Ps[wid][gq    ][nt * 8 + 2 * tq] = p0;
            *(float2*)&Ps[wid][gq + 8][nt * 8 + 2 * tq] = p1;
        }
        __syncwarp();

        // --- O += P @ V ---
#pragma unroll
        for (int ks = 0; ks < 8; ks++) {
            uint32_t pf[4];
            pf[0] = __float_as_uint(Ps[wid][gq    ][8 * ks + tq    ]);
            pf[1] = __float_as_uint(Ps[wid][gq + 8][8 * ks + tq    ]);
            pf[2] = __float_as_uint(Ps[wid][gq    ][8 * ks + tq + 4]);
            pf[3] = __float_as_uint(Ps[wid][gq + 8][8 * ks + tq + 4]);
#pragma unroll
            for (int d4 = 0; d4 < 4; d4++) {
                uint32_t bfr[2];
                bfr[0] = __float_as_uint(Vs[8 * ks + tq    ][d4 * 8 + gq]);
                bfr[1] = __float_as_uint(Vs[8 * ks + tq + 4][d4 * 8 + gq]);
                mma_tf32(o[d4], pf, bfr, o[d4]);
            }
        }
        __syncwarp();
    }

    // --- write output ---
    float inv0 = 1.0f / l0;
    float inv1 = 1.0f / l1;
#pragma unroll
    for (int d4 = 0; d4 < 4; d4++) {
        int col = h * D_ + d4 * 8 + 2 * tq;
        *(float2*)(att + (tokbase + r0) * C_ + col) =
            make_float2(o[d4][0] * inv0, o[d4][1] * inv0);
        *(float2*)(att + (tokbase + r1) * C_ + col) =
            make_float2(o[d4][2] * inv1, o[d4][3] * inv1);
    }
}

// ---------------------------------------------------------------------------
// Launch
// ---------------------------------------------------------------------------
extern "C" void kernel_launch(void* const* d_in, const int* in_sizes, int n_in,
                              void* d_out, int out_size) {
    const float* x      = (const float*)d_in[0];
    const float* wq     = (const float*)d_in[1];
    const float* wk     = (const float*)d_in[2];
    const float* wv     = (const float*)d_in[3];
    const float* w_proj = (const float*)d_in[4];
    const float* b_proj = (const float*)d_in[5];
    const float* w1     = (const float*)d_in[6];
    const float* b1     = (const float*)d_in[7];
    const float* w2     = (const float*)d_in[8];
    const float* b2     = (const float*)d_in[9];
    const float* ln1_g  = (const float*)d_in[10];
    const float* ln1_b  = (const float*)d_in[11];
    const float* ln2_g  = (const float*)d_in[12];
    const float* ln2_b  = (const float*)d_in[13];
    float* out = (float*)d_out;

    float *p_h, *p_qkv, *p_att, *p_xmid, *p_h2, *p_ffn;
    float *p_wqkvT, *p_wprojT, *p_w1T, *p_w2T;
    cudaGetSymbolAddress((void**)&p_h,      g_h);
    cudaGetSymbolAddress((void**)&p_qkv,    g_qkv);
    cudaGetSymbolAddress((void**)&p_att,    g_att);
    cudaGetSymbolAddress((void**)&p_xmid,   g_xmid);
    cudaGetSymbolAddress((void**)&p_h2,     g_h2);
    cudaGetSymbolAddress((void**)&p_ffn,    g_ffn);
    cudaGetSymbolAddress((void**)&p_wqkvT,  g_wqkvT);
    cudaGetSymbolAddress((void**)&p_wprojT, g_wprojT);
    cudaGetSymbolAddress((void**)&p_w1T,    g_w1T);
    cudaGetSymbolAddress((void**)&p_w2T,    g_w2T);

    // weight prep
    pack_wqkvT_kernel<<<(QKV_N * C_ + 255) / 256, 256>>>(wq, wk, wv, p_wqkvT);
    transpose_kernel<<<(C_ * C_ + 255) / 256, 256>>>(w_proj, p_wprojT, C_, C_);
    transpose_kernel<<<(C_ * FF_ + 255) / 256, 256>>>(w1, p_w1T, C_, FF_);
    transpose_kernel<<<(FF_ * C_ + 255) / 256, 256>>>(w2, p_w2T, FF_, C_);

    // 1. h = ln1(x)
    layernorm_kernel<<<M_TOK / 8, 256>>>(x, ln1_g, ln1_b, p_h);

    // 2. qkv = h @ Wqkv
    gemm_mma<0><<<dim3(QKV_N / 128, M_TOK / 128), 256>>>(
        p_h, p_wqkvT, p_qkv, nullptr, nullptr, M_TOK, QKV_N, C_);

    // 3. causal attention (tensor cores)
    attn_tc_kernel<<<dim3(B_ * H_, T_ / 64), 128>>>(p_qkv, p_att);

    // 4. xmid = x + att @ w_proj + b_proj
    gemm_mma<2><<<dim3(C_ / 128, M_TOK / 128), 256>>>(
        p_att, p_wprojT, p_xmid, b_proj, x, M_TOK, C_, C_);

    // 5. h2 = ln2(xmid)
    layernorm_kernel<<<M_TOK / 8, 256>>>(p_xmid, ln2_g, ln2_b, p_h2);

    // 6. ffn = relu(h2 @ w1 + b1)
    gemm_mma<1><<<dim3(FF_ / 128, M_TOK / 128), 256>>>(
        p_h2, p_w1T, p_ffn, b1, nullptr, M_TOK, FF_, C_);

    // 7. out = xmid + ffn @ w2 + b2
    gemm_mma<2><<<dim3(C_ / 128, M_TOK / 128), 256>>>(
        p_ffn, p_w2T, out, b2, p_xmid, M_TOK, C_, FF_);
}

// round 6
// speedup vs baseline: 2.6159x; 1.4563x over previous
#include <cuda_runtime.h>
#include <cstdint>

// Problem constants
#define B_    16
#define T_    1024
#define C_    256
#define H_    8
#define D_    32
#define M_TOK (B_ * T_)      // 16384 tokens
#define FF_   (4 * C_)       // 1024
#define QKV_N (3 * C_)       // 768
#define ATT_SCALE 0.0625f
#define LN_EPS 1e-5f

// ---------------------------------------------------------------------------
// Scratch (device globals)
// ---------------------------------------------------------------------------
__device__ float g_h     [M_TOK * C_];
__device__ float g_qkv   [M_TOK * QKV_N];
__device__ float g_att   [M_TOK * C_];
__device__ float g_xmid  [M_TOK * C_];
__device__ float g_h2    [M_TOK * C_];
__device__ float g_ffn   [M_TOK * FF_];
__device__ float g_wqkvT [QKV_N * C_];   // [N=768][K=256]
__device__ float g_wprojT[C_ * C_];      // [N=256][K=256]
__device__ float g_w1T   [FF_ * C_];     // [N=1024][K=256]
__device__ float g_w2T   [C_ * FF_];     // [N=256][K=1024]

// ---------------------------------------------------------------------------
// Small helpers
// ---------------------------------------------------------------------------
__device__ __forceinline__ float tf32_rn(float x) {
    float y;
    asm("cvt.rna.tf32.f32 %0, %1;" : "=f"(y) : "f"(x));
    return y;
}
__device__ __forceinline__ void mma_tf32(float* d,
                                         const uint32_t* a, const uint32_t* b,
                                         const float* c) {
    asm volatile(
        "mma.sync.aligned.m16n8k8.row.col.f32.tf32.tf32.f32 "
        "{%0,%1,%2,%3}, {%4,%5,%6,%7}, {%8,%9}, {%10,%11,%12,%13};"
        : "=f"(d[0]), "=f"(d[1]), "=f"(d[2]), "=f"(d[3])
        : "r"(a[0]), "r"(a[1]), "r"(a[2]), "r"(a[3]),
          "r"(b[0]), "r"(b[1]),
          "f"(c[0]), "f"(c[1]), "f"(c[2]), "f"(c[3]));
}
// swizzled column for element (row, k) in a [rows][32] tile
__device__ __forceinline__ int swz(int row, int k) {
    return k ^ (8 * (row & 3)) ^ (4 * ((row >> 2) & 1));
}

// ---------------------------------------------------------------------------
// Weight pre-processing
// ---------------------------------------------------------------------------
__global__ void pack_wqkvT_kernel(const float* __restrict__ wq,
                                  const float* __restrict__ wk,
                                  const float* __restrict__ wv,
                                  float* __restrict__ wqkvT) {
    int i = blockIdx.x * blockDim.x + threadIdx.x;   // i = n*256 + c
    if (i >= QKV_N * C_) return;
    int n = i / C_;
    int c = i % C_;
    const float* w = (n < C_) ? wq : ((n < 2 * C_) ? wk : wv);
    int nn = n & (C_ - 1);
    int h = nn >> 5;
    int d = nn & 31;
    wqkvT[i] = w[((size_t)h * C_ + c) * D_ + d];
}

__global__ void transpose_kernel(const float* __restrict__ src,
                                 float* __restrict__ dst, int rows, int cols) {
    int i = blockIdx.x * blockDim.x + threadIdx.x;
    if (i >= rows * cols) return;
    int r = i / cols;
    int c = i % cols;
    dst[(size_t)c * rows + r] = src[i];
}

// ---------------------------------------------------------------------------
// LayerNorm: one warp per 256-float row
// ---------------------------------------------------------------------------
__global__ __launch_bounds__(256) void layernorm_kernel(
    const float* __restrict__ in, const float* __restrict__ g,
    const float* __restrict__ b, float* __restrict__ out) {
    int warp = threadIdx.x >> 5;
    int lane = threadIdx.x & 31;
    int row  = blockIdx.x * 8 + warp;

    const float4* rp = (const float4*)(in + (size_t)row * C_);
    float4 v0 = rp[lane];
    float4 v1 = rp[lane + 32];

    float s  = v0.x + v0.y + v0.z + v0.w + v1.x + v1.y + v1.z + v1.w;
    float ss = v0.x * v0.x + v0.y * v0.y + v0.z * v0.z + v0.w * v0.w
             + v1.x * v1.x + v1.y * v1.y + v1.z * v1.z + v1.w * v1.w;
#pragma unroll
    for (int off = 16; off; off >>= 1) {
        s  += __shfl_xor_sync(0xffffffffu, s,  off);
        ss += __shfl_xor_sync(0xffffffffu, ss, off);
    }
    float mean = s * (1.0f / C_);
    float var  = ss * (1.0f / C_) - mean * mean;
    float inv  = rsqrtf(var + LN_EPS);

    const float4* gp = (const float4*)g;
    const float4* bp = (const float4*)b;
    float4 g0 = gp[lane], g1 = gp[lane + 32];
    float4 b0 = bp[lane], b1 = bp[lane + 32];

    float4 o0, o1;
    o0.x = (v0.x - mean) * inv * g0.x + b0.x;
    o0.y = (v0.y - mean) * inv * g0.y + b0.y;
    o0.z = (v0.z - mean) * inv * g0.z + b0.z;
    o0.w = (v0.w - mean) * inv * g0.w + b0.w;
    o1.x = (v1.x - mean) * inv * g1.x + b1.x;
    o1.y = (v1.y - mean) * inv * g1.y + b1.y;
    o1.z = (v1.z - mean) * inv * g1.z + b1.z;
    o1.w = (v1.w - mean) * inv * g1.w + b1.w;

    float4* op = (float4*)(out + (size_t)row * C_);
    op[lane]      = o0;
    op[lane + 32] = o1;
}

// ---------------------------------------------------------------------------
// tf32 mma.sync GEMM: C[M,N] = A[M,K] @ Bt[N,K]^T (+ epilogue)
// CTA tile 128(M) x 256(N), BK=32, 256 threads = 8 warps (2m x 4n),
// warp tile 64x64. Smem layout: [row][32] with XOR swizzle (conflict-free
// float4 stores AND conflict-free fragment loads).
// EPI: 0 = plain, 1 = +bias+relu, 2 = +bias+residual
// ---------------------------------------------------------------------------
template <int EPI>
__global__ __launch_bounds__(256, 1) void gemm_mma(
    const float* __restrict__ A, const float* __restrict__ Bt,
    float* __restrict__ Cm, const float* __restrict__ bias,
    const float* __restrict__ res, int M, int N, int K) {
    __shared__ float As[128 * 32];   // 16 KB
    __shared__ float Bs[256 * 32];   // 32 KB

    const int tid  = threadIdx.x;
    const int wid  = tid >> 5;
    const int lane = tid & 31;
    const int wm   = (wid & 1) * 64;        // warp row offset (0/64)
    const int wn   = (wid >> 1) * 64;       // warp col offset (0/64/128/192)
    const int gq   = lane >> 2;             // 0..7
    const int tq   = lane & 3;              // 0..3
    const int brow = blockIdx.y * 128;
    const int bcol = blockIdx.x * 256;

    float acc[4][8][4];
#pragma unroll
    for (int i = 0; i < 4; i++)
#pragma unroll
        for (int j = 0; j < 8; j++)
#pragma unroll
            for (int q = 0; q < 4; q++) acc[i][j][q] = 0.0f;

    const float* Ag = A + (size_t)brow * K;
    const float* Bg = Bt + (size_t)bcol * K;

    // per-thread tile-copy geometry (row = e>>3 , c4 = e&7)
    float4 pa[4], pb[8];
#pragma unroll
    for (int i = 0; i < 4; i++) {
        int e = tid + i * 256;
        pa[i] = *(const float4*)(Ag + (size_t)(e >> 3) * K + (e & 7) * 4);
    }
#pragma unroll
    for (int i = 0; i < 8; i++) {
        int e = tid + i * 256;
        pb[i] = *(const float4*)(Bg + (size_t)(e >> 3) * K + (e & 7) * 4);
    }

    const int KC = K >> 5;
    for (int kc = 0; kc < KC; kc++) {
        // store current chunk (tf32-rounded, swizzled, float4)
#pragma unroll
        for (int i = 0; i < 4; i++) {
            int e = tid + i * 256;
            int r = e >> 3, c4 = e & 7;
            int col = swz(r, c4 * 4);
            float4 v;
            v.x = tf32_rn(pa[i].x); v.y = tf32_rn(pa[i].y);
            v.z = tf32_rn(pa[i].z); v.w = tf32_rn(pa[i].w);
            *(float4*)&As[r * 32 + col] = v;
        }
#pragma unroll
        for (int i = 0; i < 8; i++) {
            int e = tid + i * 256;
            int r = e >> 3, c4 = e & 7;
            int col = swz(r, c4 * 4);
            float4 v;
            v.x = tf32_rn(pb[i].x); v.y = tf32_rn(pb[i].y);
            v.z = tf32_rn(pb[i].z); v.w = tf32_rn(pb[i].w);
            *(float4*)&Bs[r * 32 + col] = v;
        }
        __syncthreads();

        // prefetch next chunk
        if (kc + 1 < KC) {
            const float* Agn = Ag + (kc + 1) * 32;
            const float* Bgn = Bg + (kc + 1) * 32;
#pragma unroll
            for (int i = 0; i < 4; i++) {
                int e = tid + i * 256;
                pa[i] = *(const float4*)(Agn + (size_t)(e >> 3) * K + (e & 7) * 4);
            }
#pragma unroll
            for (int i = 0; i < 8; i++) {
                int e = tid + i * 256;
                pb[i] = *(const float4*)(Bgn + (size_t)(e >> 3) * K + (e & 7) * 4);
            }
        }

        // compute: 4 k-steps of 8
#pragma unroll
        for (int ks = 0; ks < 4; ks++) {
            // swizzled col for (row with low bits = gq, k = ks*8 + tq [+4])
            const int colA  = (ks * 8 + tq) ^ (8 * (gq & 3)) ^ (4 * ((gq >> 2) & 1));
            const int colA4 = colA ^ 4;

            uint32_t afr[4][4];
#pragma unroll
            for (int mt = 0; mt < 4; mt++) {
                int m0 = wm + mt * 16;
                afr[mt][0] = __float_as_uint(As[(m0 + gq    ) * 32 + colA ]);
                afr[mt][1] = __float_as_uint(As[(m0 + gq + 8) * 32 + colA ]);
                afr[mt][2] = __float_as_uint(As[(m0 + gq    ) * 32 + colA4]);
                afr[mt][3] = __float_as_uint(As[(m0 + gq + 8) * 32 + colA4]);
            }
            uint32_t bfr[8][2];
#pragma unroll
            for (int nt = 0; nt < 8; nt++) {
                int n0 = wn + nt * 8;
                bfr[nt][0] = __float_as_uint(Bs[(n0 + gq) * 32 + colA ]);
                bfr[nt][1] = __float_as_uint(Bs[(n0 + gq) * 32 + colA4]);
            }
#pragma unroll
            for (int mt = 0; mt < 4; mt++)
#pragma unroll
                for (int nt = 0; nt < 8; nt++)
                    mma_tf32(acc[mt][nt], afr[mt], bfr[nt], acc[mt][nt]);
        }
        __syncthreads();
    }

    // epilogue
#pragma unroll
    for (int mt = 0; mt < 4; mt++) {
        int row0 = brow + wm + mt * 16 + gq;
#pragma unroll
        for (int half = 0; half < 2; half++) {
            int row = row0 + half * 8;
            float* outr = Cm + (size_t)row * N;
            const float* resr = (EPI == 2) ? (res + (size_t)row * N) : nullptr;
#pragma unroll
            for (int nt = 0; nt < 8; nt++) {
                int col = bcol + wn + nt * 8 + tq * 2;
                float2 v;
                v.x = acc[mt][nt][half * 2 + 0];
                v.y = acc[mt][nt][half * 2 + 1];
                if (EPI != 0) {
                    v.x += bias[col + 0];
                    v.y += bias[col + 1];
                }
                if (EPI == 1) {
                    v.x = fmaxf(v.x, 0.0f);
                    v.y = fmaxf(v.y, 0.0f);
                }
                if (EPI == 2) {
                    float2 rr = *(const float2*)(resr + col);
                    v.x += rr.x;
                    v.y += rr.y;
                }
                *(float2*)(outr + col) = v;
            }
        }
    }
}

// ---------------------------------------------------------------------------
// Tensor-core causal flash attention (tf32 mma.sync), unchanged from R5.
// ---------------------------------------------------------------------------
#define AT_PAD  40
#define AT_PPAD 72

__global__ __launch_bounds__(128) void attn_tc_kernel(
    const float* __restrict__ qkv, float* __restrict__ att) {
    __shared__ float Qs[64][33];
    __shared__ float Ks[64][AT_PAD];
    __shared__ float Vs[64][AT_PAD];
    __shared__ float Ps[4][16][AT_PPAD];

    const int bh = blockIdx.x;
    const int b  = bh >> 3;
    const int h  = bh & 7;
    const int qt = blockIdx.y;
    const int tid  = threadIdx.x;
    const int wid  = tid >> 5;
    const int lane = tid & 31;
    const int gq   = lane >> 2;
    const int tq   = lane & 3;
    const size_t tokbase = (size_t)b * T_;
    const int qrow0 = qt * 64;
    const int m0 = wid * 16;

#pragma unroll
    for (int i = 0; i < 4; i++) {
        int e = tid + i * 128;
        int r = e >> 3, c4 = e & 7;
        float4 v = *(const float4*)(qkv + (tokbase + qrow0 + r) * QKV_N + h * D_ + c4 * 4);
        Qs[r][c4 * 4 + 0] = tf32_rn(v.x * ATT_SCALE);
        Qs[r][c4 * 4 + 1] = tf32_rn(v.y * ATT_SCALE);
        Qs[r][c4 * 4 + 2] = tf32_rn(v.z * ATT_SCALE);
        Qs[r][c4 * 4 + 3] = tf32_rn(v.w * ATT_SCALE);
    }
    __syncthreads();

    uint32_t qf[4][4];
#pragma unroll
    for (int ks = 0; ks < 4; ks++) {
        qf[ks][0] = __float_as_uint(Qs[m0 + gq    ][8 * ks + tq    ]);
        qf[ks][1] = __float_as_uint(Qs[m0 + gq + 8][8 * ks + tq    ]);
        qf[ks][2] = __float_as_uint(Qs[m0 + gq    ][8 * ks + tq + 4]);
        qf[ks][3] = __float_as_uint(Qs[m0 + gq + 8][8 * ks + tq + 4]);
    }

    const int r0 = qrow0 + m0 + gq;
    const int r1 = r0 + 8;

    float mrow0 = -1e30f, mrow1 = -1e30f;
    float l0 = 0.0f, l1 = 0.0f;
    float o[4][4];
#pragma unroll
    for (int i = 0; i < 4; i++)
#pragma unroll
        for (int j = 0; j < 4; j++) o[i][j] = 0.0f;

    for (int s0 = 0; s0 <= qrow0; s0 += 64) {
        __syncthreads();
#pragma unroll
        for (int i = 0; i < 4; i++) {
            int e = tid + i * 128;
            int r = e >> 3, c4 = e & 7;
            const float* base = qkv + (tokbase + s0 + r) * QKV_N + h * D_ + c4 * 4;
            float4 kv = *(const float4*)(base + C_);
            float4 vv = *(const float4*)(base + 2 * C_);
            Ks[r][c4 * 4 + 0] = tf32_rn(kv.x);
            Ks[r][c4 * 4 + 1] = tf32_rn(kv.y);
            Ks[r][c4 * 4 + 2] = tf32_rn(kv.z);
            Ks[r][c4 * 4 + 3] = tf32_rn(kv.w);
            Vs[r][c4 * 4 + 0] = tf32_rn(vv.x);
            Vs[r][c4 * 4 + 1] = tf32_rn(vv.y);
            Vs[r][c4 * 4 + 2] = tf32_rn(vv.z);
            Vs[r][c4 * 4 + 3] = tf32_rn(vv.w);
        }
        __syncthreads();

        float S[8][4];
#pragma unroll
        for (int nt = 0; nt < 8; nt++) {
            S[nt][0] = S[nt][1] = S[nt][2] = S[nt][3] = 0.0f;
#pragma unroll
            for (int ks = 0; ks < 4; ks++) {
                uint32_t bfr[2];
                bfr[0] = __float_as_uint(Ks[nt * 8 + gq][8 * ks + tq    ]);
                bfr[1] = __float_as_uint(Ks[nt * 8 + gq][8 * ks + tq + 4]);
                mma_tf32(S[nt], qf[ks], bfr, S[nt]);
            }
        }

        if (s0 == qrow0) {
#pragma unroll
            for (int nt = 0; nt < 8; nt++) {
                int col = s0 + nt * 8 + 2 * tq;
                if (col     > r0) S[nt][0] = -1e30f;
                if (col + 1 > r0) S[nt][1] = -1e30f;
                if (col     > r1) S[nt][2] = -1e30f;
                if (col + 1 > r1) S[nt][3] = -1e30f;
            }
        }

        float mx0 = -1e30f, mx1 = -1e30f;
#pragma unroll
        for (int nt = 0; nt < 8; nt++) {
            mx0 = fmaxf(mx0, fmaxf(S[nt][0], S[nt][1]));
            mx1 = fmaxf(mx1, fmaxf(S[nt][2], S[nt][3]));
        }
        mx0 = fmaxf(mx0, __shfl_xor_sync(0xffffffffu, mx0, 1));
        mx0 = fmaxf(mx0, __shfl_xor_sync(0xffffffffu, mx0, 2));
        mx1 = fmaxf(mx1, __shfl_xor_sync(0xffffffffu, mx1, 1));
        mx1 = fmaxf(mx1, __shfl_xor_sync(0xffffffffu, mx1, 2));

        float mn0 = fmaxf(mrow0, mx0);
        float mn1 = fmaxf(mrow1, mx1);
        float a0 = __expf(mrow0 - mn0);
        float a1 = __expf(mrow1 - mn1);
        mrow0 = mn0;
        mrow1 = mn1;

        float sum0 = 0.0f, sum1 = 0.0f;
#pragma unroll
        for (int nt = 0; nt < 8; nt++) {
            S[nt][0] = __expf(S[nt][0] - mn0);
            S[nt][1] = __expf(S[nt][1] - mn0);
            S[nt][2] = __expf(S[nt][2] - mn1);
            S[nt][3] = __expf(S[nt][3] - mn1);
            sum0 += S[nt][0] + S[nt][1];
            sum1 += S[nt][2] + S[nt][3];
        }
        sum0 += __shfl_xor_sync(0xffffffffu, sum0, 1);
        sum0 += __shfl_xor_sync(0xffffffffu, sum0, 2);
        sum1 += __shfl_xor_sync(0xffffffffu, sum1, 1);
        sum1 += __shfl_xor_sync(0xffffffffu, sum1, 2);
        l0 = l0 * a0 + sum0;
        l1 = l1 * a1 + sum1;

#pragma unroll
        for (int d4 = 0; d4 < 4; d4++) {
            o[d4][0] *= a0;
            o[d4][1] *= a0;
            o[d4][2] *= a1;
            o[d4][3] *= a1;
        }

#pragma unroll
        for (int nt = 0; nt < 8; nt++) {
            float2 p0 = make_float2(tf32_rn(S[nt][0]), tf32_rn(S[nt][1]));
            float2 p1 = make_float2(tf32_rn(S[nt][2]), tf32_rn(S[nt][3]));
            *(float2*)&Ps[wid][gq    ][nt * 8 + 2 * tq] = p0;
            *(float2*)&Ps[wid][gq + 8][nt * 8 + 2 * tq] = p1;
        }
        __syncwarp();

#pragma unroll
        for (int ks = 0; ks < 8; ks++) {
            uint32_t pf[4];
            pf[0] = __float_as_uint(Ps[wid][gq    ][8 * ks + tq    ]);
            pf[1] = __float_as_uint(Ps[wid][gq + 8][8 * ks + tq    ]);
            pf[2] = __float_as_uint(Ps[wid][gq    ][8 * ks + tq + 4]);
            pf[3] = __float_as_uint(Ps[wid][gq + 8][8 * ks + tq + 4]);
#pragma unroll
            for (int d4 = 0; d4 < 4; d4++) {
                uint32_t bfr[2];
                bfr[0] = __float_as_uint(Vs[8 * ks + tq    ][d4 * 8 + gq]);
                bfr[1] = __float_as_uint(Vs[8 * ks + tq + 4][d4 * 8 + gq]);
                mma_tf32(o[d4], pf, bfr, o[d4]);
            }
        }
        __syncwarp();
    }

    float inv0 = 1.0f / l0;
    float inv1 = 1.0f / l1;
#pragma unroll
    for (int d4 = 0; d4 < 4; d4++) {
        int col = h * D_ + d4 * 8 + 2 * tq;
        *(float2*)(att + (tokbase + r0) * C_ + col) =
            make_float2(o[d4][0] * inv0, o[d4][1] * inv0);
        *(float2*)(att + (tokbase + r1) * C_ + col) =
            make_float2(o[d4][2] * inv1, o[d4][3] * inv1);
    }
}

// ---------------------------------------------------------------------------
// Launch
// ---------------------------------------------------------------------------
extern "C" void kernel_launch(void* const* d_in, const int* in_sizes, int n_in,
                              void* d_out, int out_size) {
    const float* x      = (const float*)d_in[0];
    const float* wq     = (const float*)d_in[1];
    const float* wk     = (const float*)d_in[2];
    const float* wv     = (const float*)d_in[3];
    const float* w_proj = (const float*)d_in[4];
    const float* b_proj = (const float*)d_in[5];
    const float* w1     = (const float*)d_in[6];
    const float* b1     = (const float*)d_in[7];
    const float* w2     = (const float*)d_in[8];
    const float* b2     = (const float*)d_in[9];
    const float* ln1_g  = (const float*)d_in[10];
    const float* ln1_b  = (const float*)d_in[11];
    const float* ln2_g  = (const float*)d_in[12];
    const float* ln2_b  = (const float*)d_in[13];
    float* out = (float*)d_out;

    float *p_h, *p_qkv, *p_att, *p_xmid, *p_h2, *p_ffn;
    float *p_wqkvT, *p_wprojT, *p_w1T, *p_w2T;
    cudaGetSymbolAddress((void**)&p_h,      g_h);
    cudaGetSymbolAddress((void**)&p_qkv,    g_qkv);
    cudaGetSymbolAddress((void**)&p_att,    g_att);
    cudaGetSymbolAddress((void**)&p_xmid,   g_xmid);
    cudaGetSymbolAddress((void**)&p_h2,     g_h2);
    cudaGetSymbolAddress((void**)&p_ffn,    g_ffn);
    cudaGetSymbolAddress((void**)&p_wqkvT,  g_wqkvT);
    cudaGetSymbolAddress((void**)&p_wprojT, g_wprojT);
    cudaGetSymbolAddress((void**)&p_w1T,    g_w1T);
    cudaGetSymbolAddress((void**)&p_w2T,    g_w2T);

    // weight prep
    pack_wqkvT_kernel<<<(QKV_N * C_ + 255) / 256, 256>>>(wq, wk, wv, p_wqkvT);
    transpose_kernel<<<(C_ * C_ + 255) / 256, 256>>>(w_proj, p_wprojT, C_, C_);
    transpose_kernel<<<(C_ * FF_ + 255) / 256, 256>>>(w1, p_w1T, C_, FF_);
    transpose_kernel<<<(FF_ * C_ + 255) / 256, 256>>>(w2, p_w2T, FF_, C_);

    // 1. h = ln1(x)
    layernorm_kernel<<<M_TOK / 8, 256>>>(x, ln1_g, ln1_b, p_h);

    // 2. qkv = h @ Wqkv  (N=768 -> 3 col-blocks of 256)
    gemm_mma<0><<<dim3(QKV_N / 256, M_TOK / 128), 256>>>(
        p_h, p_wqkvT, p_qkv, nullptr, nullptr, M_TOK, QKV_N, C_);

    // 3. causal attention (tensor cores)
    attn_tc_kernel<<<dim3(B_ * H_, T_ / 64), 128>>>(p_qkv, p_att);

    // 4. xmid = x + att @ w_proj + b_proj  (N=256)
    gemm_mma<2><<<dim3(C_ / 256, M_TOK / 128), 256>>>(
        p_att, p_wprojT, p_xmid, b_proj, x, M_TOK, C_, C_);

    // 5. h2 = ln2(xmid)
    layernorm_kernel<<<M_TOK / 8, 256>>>(p_xmid, ln2_g, ln2_b, p_h2);

    // 6. ffn = relu(h2 @ w1 + b1)  (N=1024)
    gemm_mma<1><<<dim3(FF_ / 256, M_TOK / 128), 256>>>(
        p_h2, p_w1T, p_ffn, b1, nullptr, M_TOK, FF_, C_);

    // 7. out = xmid + ffn @ w2 + b2  (N=256, K=1024)
    gemm_mma<2><<<dim3(C_ / 256, M_TOK / 128), 256>>>(
        p_ffn, p_w2T, out, b2, p_xmid, M_TOK, C_, FF_);
}

// round 7
// speedup vs baseline: 2.6329x; 1.0065x over previous
#include <cuda_runtime.h>
#include <cstdint>

// Problem constants
#define B_    16
#define T_    1024
#define C_    256
#define H_    8
#define D_    32
#define M_TOK (B_ * T_)      // 16384 tokens
#define FF_   (4 * C_)       // 1024
#define QKV_N (3 * C_)       // 768
#define ATT_SCALE 0.0625f
#define LN_EPS 1e-5f

// ---------------------------------------------------------------------------
// Scratch (device globals)
// ---------------------------------------------------------------------------
__device__ float g_h     [M_TOK * C_];
__device__ float g_qkv   [M_TOK * QKV_N];
__device__ float g_att   [M_TOK * C_];
__device__ float g_xmid  [M_TOK * C_];
__device__ float g_h2    [M_TOK * C_];
__device__ float g_ffn   [M_TOK * FF_];
__device__ float g_wqkvT [QKV_N * C_];   // [N=768][K=256]
__device__ float g_wprojT[C_ * C_];      // [N=256][K=256]
__device__ float g_w1T   [FF_ * C_];     // [N=1024][K=256]
__device__ float g_w2T   [C_ * FF_];     // [N=256][K=1024]

// ---------------------------------------------------------------------------
// Small helpers
// ---------------------------------------------------------------------------
__device__ __forceinline__ float tf32_rn(float x) {
    float y;
    asm("cvt.rna.tf32.f32 %0, %1;" : "=f"(y) : "f"(x));
    return y;
}
__device__ __forceinline__ void mma_tf32(float* d,
                                         const uint32_t* a, const uint32_t* b,
                                         const float* c) {
    asm volatile(
        "mma.sync.aligned.m16n8k8.row.col.f32.tf32.tf32.f32 "
        "{%0,%1,%2,%3}, {%4,%5,%6,%7}, {%8,%9}, {%10,%11,%12,%13};"
        : "=f"(d[0]), "=f"(d[1]), "=f"(d[2]), "=f"(d[3])
        : "r"(a[0]), "r"(a[1]), "r"(a[2]), "r"(a[3]),
          "r"(b[0]), "r"(b[1]),
          "f"(c[0]), "f"(c[1]), "f"(c[2]), "f"(c[3]));
}
// swizzled column for element (row, k) in a [rows][32] tile
__device__ __forceinline__ int swz(int row, int k) {
    return k ^ (8 * (row & 3)) ^ (4 * ((row >> 2) & 1));
}

// ---------------------------------------------------------------------------
// Weight pre-processing: single merged kernel
//   region 0: pack wq/wk/wv -> wqkvT [768][256]       (196608 elems)
//   region 1: w_proj  (256x256)  -> wprojT [256][256] ( 65536 elems)
//   region 2: w1      (256x1024) -> w1T    [1024][256](262144 elems)
//   region 3: w2      (1024x256) -> w2T    [256][1024](262144 elems)
// ---------------------------------------------------------------------------
#define PREP_TOTAL (QKV_N * C_ + C_ * C_ + C_ * FF_ + FF_ * C_)

__global__ void prep_weights_kernel(
    const float* __restrict__ wq, const float* __restrict__ wk,
    const float* __restrict__ wv, const float* __restrict__ w_proj,
    const float* __restrict__ w1, const float* __restrict__ w2,
    float* __restrict__ wqkvT, float* __restrict__ wprojT,
    float* __restrict__ w1T, float* __restrict__ w2T) {
    int i = blockIdx.x * blockDim.x + threadIdx.x;
    if (i < QKV_N * C_) {                       // i = n*256 + c
        int n = i / C_;
        int c = i % C_;
        const float* w = (n < C_) ? wq : ((n < 2 * C_) ? wk : wv);
        int nn = n & (C_ - 1);
        wqkvT[i] = w[((size_t)(nn >> 5) * C_ + c) * D_ + (nn & 31)];
        return;
    }
    i -= QKV_N * C_;
    if (i < C_ * C_) {                          // w_proj transpose
        int r = i / C_, c = i % C_;
        wprojT[c * C_ + r] = w_proj[i];
        return;
    }
    i -= C_ * C_;
    if (i < C_ * FF_) {                         // w1 transpose (256 x 1024)
        int r = i / FF_, c = i % FF_;
        w1T[c * C_ + r] = w1[i];
        return;
    }
    i -= C_ * FF_;
    if (i < FF_ * C_) {                         // w2 transpose (1024 x 256)
        int r = i / C_, c = i % C_;
        w2T[c * FF_ + r] = w2[i];
    }
}

// ---------------------------------------------------------------------------
// LayerNorm: one warp per 256-float row
// ---------------------------------------------------------------------------
__global__ __launch_bounds__(256) void layernorm_kernel(
    const float* __restrict__ in, const float* __restrict__ g,
    const float* __restrict__ b, float* __restrict__ out) {
    int warp = threadIdx.x >> 5;
    int lane = threadIdx.x & 31;
    int row  = blockIdx.x * 8 + warp;

    const float4* rp = (const float4*)(in + (size_t)row * C_);
    float4 v0 = rp[lane];
    float4 v1 = rp[lane + 32];

    float s  = v0.x + v0.y + v0.z + v0.w + v1.x + v1.y + v1.z + v1.w;
    float ss = v0.x * v0.x + v0.y * v0.y + v0.z * v0.z + v0.w * v0.w
             + v1.x * v1.x + v1.y * v1.y + v1.z * v1.z + v1.w * v1.w;
#pragma unroll
    for (int off = 16; off; off >>= 1) {
        s  += __shfl_xor_sync(0xffffffffu, s,  off);
        ss += __shfl_xor_sync(0xffffffffu, ss, off);
    }
    float mean = s * (1.0f / C_);
    float var  = ss * (1.0f / C_) - mean * mean;
    float inv  = rsqrtf(var + LN_EPS);

    const float4* gp = (const float4*)g;
    const float4* bp = (const float4*)b;
    float4 g0 = gp[lane], g1 = gp[lane + 32];
    float4 b0 = bp[lane], b1 = bp[lane + 32];

    float4 o0, o1;
    o0.x = (v0.x - mean) * inv * g0.x + b0.x;
    o0.y = (v0.y - mean) * inv * g0.y + b0.y;
    o0.z = (v0.z - mean) * inv * g0.z + b0.z;
    o0.w = (v0.w - mean) * inv * g0.w + b0.w;
    o1.x = (v1.x - mean) * inv * g1.x + b1.x;
    o1.y = (v1.y - mean) * inv * g1.y + b1.y;
    o1.z = (v1.z - mean) * inv * g1.z + b1.z;
    o1.w = (v1.w - mean) * inv * g1.w + b1.w;

    float4* op = (float4*)(out + (size_t)row * C_);
    op[lane]      = o0;
    op[lane + 32] = o1;
}

// ---------------------------------------------------------------------------
// tf32 mma.sync GEMM, 2-stage smem double buffer (ONE barrier per K-chunk).
// CTA tile 128x256, BK=32, 8 warps (2m x 4n), warp tile 64x64, XOR swizzle.
// Dynamic smem: 2 * (128*32 + 256*32) floats = 96 KB.
// EPI: 0 = plain, 1 = +bias+relu, 2 = +bias+residual
// ---------------------------------------------------------------------------
#define GA_SZ (128 * 32)
#define GB_SZ (256 * 32)
#define GEMM_SMEM_BYTES (2 * (GA_SZ + GB_SZ) * 4)   // 98304

template <int EPI>
__global__ __launch_bounds__(256, 1) void gemm_mma(
    const float* __restrict__ A, const float* __restrict__ Bt,
    float* __restrict__ Cm, const float* __restrict__ bias,
    const float* __restrict__ res, int M, int N, int K) {
    extern __shared__ float dynsm[];
    // stage s: A at dynsm + s*GA_SZ, B at dynsm + 2*GA_SZ + s*GB_SZ
    float* const Abuf[2] = { dynsm, dynsm + GA_SZ };
    float* const Bbuf[2] = { dynsm + 2 * GA_SZ, dynsm + 2 * GA_SZ + GB_SZ };

    const int tid  = threadIdx.x;
    const int wid  = tid >> 5;
    const int lane = tid & 31;
    const int wm   = (wid & 1) * 64;
    const int wn   = (wid >> 1) * 64;
    const int gq   = lane >> 2;
    const int tq   = lane & 3;
    const int brow = blockIdx.y * 128;
    const int bcol = blockIdx.x * 256;

    float acc[4][8][4];
#pragma unroll
    for (int i = 0; i < 4; i++)
#pragma unroll
        for (int j = 0; j < 8; j++)
#pragma unroll
            for (int q = 0; q < 4; q++) acc[i][j][q] = 0.0f;

    const float* Ag = A + (size_t)brow * K;
    const float* Bg = Bt + (size_t)bcol * K;

    float4 pa[4], pb[8];
#pragma unroll
    for (int i = 0; i < 4; i++) {
        int e = tid + i * 256;
        pa[i] = *(const float4*)(Ag + (size_t)(e >> 3) * K + (e & 7) * 4);
    }
#pragma unroll
    for (int i = 0; i < 8; i++) {
        int e = tid + i * 256;
        pb[i] = *(const float4*)(Bg + (size_t)(e >> 3) * K + (e & 7) * 4);
    }

    const int KC = K >> 5;
    for (int kc = 0; kc < KC; kc++) {
        float* As = Abuf[kc & 1];
        float* Bs = Bbuf[kc & 1];

        // store current chunk (tf32-rounded, swizzled, float4)
#pragma unroll
        for (int i = 0; i < 4; i++) {
            int e = tid + i * 256;
            int r = e >> 3, c4 = e & 7;
            float4 v;
            v.x = tf32_rn(pa[i].x); v.y = tf32_rn(pa[i].y);
            v.z = tf32_rn(pa[i].z); v.w = tf32_rn(pa[i].w);
            *(float4*)&As[r * 32 + swz(r, c4 * 4)] = v;
        }
#pragma unroll
        for (int i = 0; i < 8; i++) {
            int e = tid + i * 256;
            int r = e >> 3, c4 = e & 7;
            float4 v;
            v.x = tf32_rn(pb[i].x); v.y = tf32_rn(pb[i].y);
            v.z = tf32_rn(pb[i].z); v.w = tf32_rn(pb[i].w);
            *(float4*)&Bs[r * 32 + swz(r, c4 * 4)] = v;
        }
        __syncthreads();   // the ONLY barrier per chunk (2-stage buffer)

        // prefetch next chunk into registers (hidden under compute)
        if (kc + 1 < KC) {
            const float* Agn = Ag + (kc + 1) * 32;
            const float* Bgn = Bg + (kc + 1) * 32;
#pragma unroll
            for (int i = 0; i < 4; i++) {
                int e = tid + i * 256;
                pa[i] = *(const float4*)(Agn + (size_t)(e >> 3) * K + (e & 7) * 4);
            }
#pragma unroll
            for (int i = 0; i < 8; i++) {
                int e = tid + i * 256;
                pb[i] = *(const float4*)(Bgn + (size_t)(e >> 3) * K + (e & 7) * 4);
            }
        }

        // compute: 4 k-steps of 8
#pragma unroll
        for (int ks = 0; ks < 4; ks++) {
            const int colA  = (ks * 8 + tq) ^ (8 * (gq & 3)) ^ (4 * ((gq >> 2) & 1));
            const int colA4 = colA ^ 4;

            uint32_t afr[4][4];
#pragma unroll
            for (int mt = 0; mt < 4; mt++) {
                int m0 = wm + mt * 16;
                afr[mt][0] = __float_as_uint(As[(m0 + gq    ) * 32 + colA ]);
                afr[mt][1] = __float_as_uint(As[(m0 + gq + 8) * 32 + colA ]);
                afr[mt][2] = __float_as_uint(As[(m0 + gq    ) * 32 + colA4]);
                afr[mt][3] = __float_as_uint(As[(m0 + gq + 8) * 32 + colA4]);
            }
            uint32_t bfr[8][2];
#pragma unroll
            for (int nt = 0; nt < 8; nt++) {
                int n0 = wn + nt * 8;
                bfr[nt][0] = __float_as_uint(Bs[(n0 + gq) * 32 + colA ]);
                bfr[nt][1] = __float_as_uint(Bs[(n0 + gq) * 32 + colA4]);
            }
#pragma unroll
            for (int mt = 0; mt < 4; mt++)
#pragma unroll
                for (int nt = 0; nt < 8; nt++)
                    mma_tf32(acc[mt][nt], afr[mt], bfr[nt], acc[mt][nt]);
        }
        // no trailing barrier: next store targets the other stage, and the
        // store 2 chunks ahead is separated from these reads by next sync.
    }

    // epilogue
#pragma unroll
    for (int mt = 0; mt < 4; mt++) {
        int row0 = brow + wm + mt * 16 + gq;
#pragma unroll
        for (int half = 0; half < 2; half++) {
            int row = row0 + half * 8;
            float* outr = Cm + (size_t)row * N;
            const float* resr = (EPI == 2) ? (res + (size_t)row * N) : nullptr;
#pragma unroll
            for (int nt = 0; nt < 8; nt++) {
                int col = bcol + wn + nt * 8 + tq * 2;
                float2 v;
                v.x = acc[mt][nt][half * 2 + 0];
                v.y = acc[mt][nt][half * 2 + 1];
                if (EPI != 0) {
                    v.x += bias[col + 0];
                    v.y += bias[col + 1];
                }
                if (EPI == 1) {
                    v.x = fmaxf(v.x, 0.0f);
                    v.y = fmaxf(v.y, 0.0f);
                }
                if (EPI == 2) {
                    float2 rr = *(const float2*)(resr + col);
                    v.x += rr.x;
                    v.y += rr.y;
                }
                *(float2*)(outr + col) = v;
            }
        }
    }
}

// ---------------------------------------------------------------------------
// Tensor-core causal flash attention (tf32 mma.sync).
// 2-stage K/V smem double buffer, register prefetch, ONE barrier per tile.
// ---------------------------------------------------------------------------
#define AT_PAD  40
#define AT_PPAD 72

__global__ __launch_bounds__(128) void attn_tc_kernel(
    const float* __restrict__ qkv, float* __restrict__ att) {
    __shared__ float Qs[64][33];
    __shared__ float Ks[2][64][AT_PAD];
    __shared__ float Vs[2][64][AT_PAD];
    __shared__ float Ps[4][16][AT_PPAD];

    const int bh = blockIdx.x;
    const int b  = bh >> 3;
    const int h  = bh & 7;
    const int qt = blockIdx.y;
    const int tid  = threadIdx.x;
    const int wid  = tid >> 5;
    const int lane = tid & 31;
    const int gq   = lane >> 2;
    const int tq   = lane & 3;
    const size_t tokbase = (size_t)b * T_;
    const int qrow0 = qt * 64;
    const int m0 = wid * 16;

    // load + scale + round Q tile (64x32)
#pragma unroll
    for (int i = 0; i < 4; i++) {
        int e = tid + i * 128;
        int r = e >> 3, c4 = e & 7;
        float4 v = *(const float4*)(qkv + (tokbase + qrow0 + r) * QKV_N + h * D_ + c4 * 4);
        Qs[r][c4 * 4 + 0] = tf32_rn(v.x * ATT_SCALE);
        Qs[r][c4 * 4 + 1] = tf32_rn(v.y * ATT_SCALE);
        Qs[r][c4 * 4 + 2] = tf32_rn(v.z * ATT_SCALE);
        Qs[r][c4 * 4 + 3] = tf32_rn(v.w * ATT_SCALE);
    }

    // prefetch K/V tile 0 into registers
    float4 rk[4], rv[4];
#pragma unroll
    for (int i = 0; i < 4; i++) {
        int e = tid + i * 128;
        int r = e >> 3, c4 = e & 7;
        const float* base = qkv + (tokbase + r) * QKV_N + h * D_ + c4 * 4;
        rk[i] = *(const float4*)(base + C_);
        rv[i] = *(const float4*)(base + 2 * C_);
    }
    __syncthreads();

    uint32_t qf[4][4];
#pragma unroll
    for (int ks = 0; ks < 4; ks++) {
        qf[ks][0] = __float_as_uint(Qs[m0 + gq    ][8 * ks + tq    ]);
        qf[ks][1] = __float_as_uint(Qs[m0 + gq + 8][8 * ks + tq    ]);
        qf[ks][2] = __float_as_uint(Qs[m0 + gq    ][8 * ks + tq + 4]);
        qf[ks][3] = __float_as_uint(Qs[m0 + gq + 8][8 * ks + tq + 4]);
    }

    const int r0 = qrow0 + m0 + gq;
    const int r1 = r0 + 8;

    float mrow0 = -1e30f, mrow1 = -1e30f;
    float l0 = 0.0f, l1 = 0.0f;
    float o[4][4];
#pragma unroll
    for (int i = 0; i < 4; i++)
#pragma unroll
        for (int j = 0; j < 4; j++) o[i][j] = 0.0f;

    for (int s0 = 0; s0 <= qrow0; s0 += 64) {
        const int buf = (s0 >> 6) & 1;

        // store prefetched tile (tf32-rounded)
#pragma unroll
        for (int i = 0; i < 4; i++) {
            int e = tid + i * 128;
            int r = e >> 3, c4 = e & 7;
            Ks[buf][r][c4 * 4 + 0] = tf32_rn(rk[i].x);
            Ks[buf][r][c4 * 4 + 1] = tf32_rn(rk[i].y);
            Ks[buf][r][c4 * 4 + 2] = tf32_rn(rk[i].z);
            Ks[buf][r][c4 * 4 + 3] = tf32_rn(rk[i].w);
            Vs[buf][r][c4 * 4 + 0] = tf32_rn(rv[i].x);
            Vs[buf][r][c4 * 4 + 1] = tf32_rn(rv[i].y);
            Vs[buf][r][c4 * 4 + 2] = tf32_rn(rv[i].z);
            Vs[buf][r][c4 * 4 + 3] = tf32_rn(rv[i].w);
        }
        __syncthreads();   // single barrier per tile

        // prefetch next tile (hidden under compute)
        if (s0 + 64 <= qrow0) {
#pragma unroll
            for (int i = 0; i < 4; i++) {
                int e = tid + i * 128;
                int r = e >> 3, c4 = e & 7;
                const float* base = qkv + (tokbase + s0 + 64 + r) * QKV_N + h * D_ + c4 * 4;
                rk[i] = *(const float4*)(base + C_);
                rv[i] = *(const float4*)(base + 2 * C_);
            }
        }

        // --- S = Q @ K^T ---
        float S[8][4];
#pragma unroll
        for (int nt = 0; nt < 8; nt++) {
            S[nt][0] = S[nt][1] = S[nt][2] = S[nt][3] = 0.0f;
#pragma unroll
            for (int ks = 0; ks < 4; ks++) {
                uint32_t bfr[2];
                bfr[0] = __float_as_uint(Ks[buf][nt * 8 + gq][8 * ks + tq    ]);
                bfr[1] = __float_as_uint(Ks[buf][nt * 8 + gq][8 * ks + tq + 4]);
                mma_tf32(S[nt], qf[ks], bfr, S[nt]);
            }
        }

        // causal mask (diagonal tile only)
        if (s0 == qrow0) {
#pragma unroll
            for (int nt = 0; nt < 8; nt++) {
                int col = s0 + nt * 8 + 2 * tq;
                if (col     > r0) S[nt][0] = -1e30f;
                if (col + 1 > r0) S[nt][1] = -1e30f;
                if (col     > r1) S[nt][2] = -1e30f;
                if (col + 1 > r1) S[nt][3] = -1e30f;
            }
        }

        // online softmax
        float mx0 = -1e30f, mx1 = -1e30f;
#pragma unroll
        for (int nt = 0; nt < 8; nt++) {
            mx0 = fmaxf(mx0, fmaxf(S[nt][0], S[nt][1]));
            mx1 = fmaxf(mx1, fmaxf(S[nt][2], S[nt][3]));
        }
        mx0 = fmaxf(mx0, __shfl_xor_sync(0xffffffffu, mx0, 1));
        mx0 = fmaxf(mx0, __shfl_xor_sync(0xffffffffu, mx0, 2));
        mx1 = fmaxf(mx1, __shfl_xor_sync(0xffffffffu, mx1, 1));
        mx1 = fmaxf(mx1, __shfl_xor_sync(0xffffffffu, mx1, 2));

        float mn0 = fmaxf(mrow0, mx0);
        float mn1 = fmaxf(mrow1, mx1);
        float a0 = __expf(mrow0 - mn0);
        float a1 = __expf(mrow1 - mn1);
        mrow0 = mn0;
        mrow1 = mn1;

        float sum0 = 0.0f, sum1 = 0.0f;
#pragma unroll
        for (int nt = 0; nt < 8; nt++) {
            S[nt][0] = __expf(S[nt][0] - mn0);
            S[nt][1] = __expf(S[nt][1] - mn0);
            S[nt][2] = __expf(S[nt][2] - mn1);
            S[nt][3] = __expf(S[nt][3] - mn1);
            sum0 += S[nt][0] + S[nt][1];
            sum1 += S[nt][2] + S[nt][3];
        }
        sum0 += __shfl_xor_sync(0xffffffffu, sum0, 1);
        sum0 += __shfl_xor_sync(0xffffffffu, sum0, 2);
        sum1 += __shfl_xor_sync(0xffffffffu, sum1, 1);
        sum1 += __shfl_xor_sync(0xffffffffu, sum1, 2);
        l0 = l0 * a0 + sum0;
        l1 = l1 * a1 + sum1;

#pragma unroll
        for (int d4 = 0; d4 < 4; d4++) {
            o[d4][0] *= a0;
            o[d4][1] *= a0;
            o[d4][2] *= a1;
            o[d4][3] *= a1;
        }

        // stage P (tf32) to per-warp smem
#pragma unroll
        for (int nt = 0; nt < 8; nt++) {
            float2 p0 = make_float2(tf32_rn(S[nt][0]), tf32_rn(S[nt][1]));
            float2 p1 = make_float2(tf32_rn(S[nt][2]), tf32_rn(S[nt][3]));
            *(float2*)&Ps[wid][gq    ][nt * 8 + 2 * tq] = p0;
            *(float2*)&Ps[wid][gq + 8][nt * 8 + 2 * tq] = p1;
        }
        __syncwarp();

        // O += P @ V
#pragma unroll
        for (int ks = 0; ks < 8; ks++) {
            uint32_t pf[4];
            pf[0] = __float_as_uint(Ps[wid][gq    ][8 * ks + tq    ]);
            pf[1] = __float_as_uint(Ps[wid][gq + 8][8 * ks + tq    ]);
            pf[2] = __float_as_uint(Ps[wid][gq    ][8 * ks + tq + 4]);
            pf[3] = __float_as_uint(Ps[wid][gq + 8][8 * ks + tq + 4]);
#pragma unroll
            for (int d4 = 0; d4 < 4; d4++) {
                uint32_t bfr[2];
                bfr[0] = __float_as_uint(Vs[buf][8 * ks + tq    ][d4 * 8 + gq]);
                bfr[1] = __float_as_uint(Vs[buf][8 * ks + tq + 4][d4 * 8 + gq]);
                mma_tf32(o[d4], pf, bfr, o[d4]);
            }
        }
        __syncwarp();
    }

    float inv0 = 1.0f / l0;
    float inv1 = 1.0f / l1;
#pragma unroll
    for (int d4 = 0; d4 < 4; d4++) {
        int col = h * D_ + d4 * 8 + 2 * tq;
        *(float2*)(att + (tokbase + r0) * C_ + col) =
            make_float2(o[d4][0] * inv0, o[d4][1] * inv0);
        *(float2*)(att + (tokbase + r1) * C_ + col) =
            make_float2(o[d4][2] * inv1, o[d4][3] * inv1);
    }
}

// ---------------------------------------------------------------------------
// Launch
// ---------------------------------------------------------------------------
extern "C" void kernel_launch(void* const* d_in, const int* in_sizes, int n_in,
                              void* d_out, int out_size) {
    const float* x      = (const float*)d_in[0];
    const float* wq     = (const float*)d_in[1];
    const float* wk     = (const float*)d_in[2];
    const float* wv     = (const float*)d_in[3];
    const float* w_proj = (const float*)d_in[4];
    const float* b_proj = (const float*)d_in[5];
    const float* w1     = (const float*)d_in[6];
    const float* b1     = (const float*)d_in[7];
    const float* w2     = (const float*)d_in[8];
    const float* b2     = (const float*)d_in[9];
    const float* ln1_g  = (const float*)d_in[10];
    const float* ln1_b  = (const float*)d_in[11];
    const float* ln2_g  = (const float*)d_in[12];
    const float* ln2_b  = (const float*)d_in[13];
    float* out = (float*)d_out;

    float *p_h, *p_qkv, *p_att, *p_xmid, *p_h2, *p_ffn;
    float *p_wqkvT, *p_wprojT, *p_w1T, *p_w2T;
    cudaGetSymbolAddress((void**)&p_h,      g_h);
    cudaGetSymbolAddress((void**)&p_qkv,    g_qkv);
    cudaGetSymbolAddress((void**)&p_att,    g_att);
    cudaGetSymbolAddress((void**)&p_xmid,   g_xmid);
    cudaGetSymbolAddress((void**)&p_h2,     g_h2);
    cudaGetSymbolAddress((void**)&p_ffn,    g_ffn);
    cudaGetSymbolAddress((void**)&p_wqkvT,  g_wqkvT);
    cudaGetSymbolAddress((void**)&p_wprojT, g_wprojT);
    cudaGetSymbolAddress((void**)&p_w1T,    g_w1T);
    cudaGetSymbolAddress((void**)&p_w2T,    g_w2T);

    cudaFuncSetAttribute(gemm_mma<0>, cudaFuncAttributeMaxDynamicSharedMemorySize, GEMM_SMEM_BYTES);
    cudaFuncSetAttribute(gemm_mma<1>, cudaFuncAttributeMaxDynamicSharedMemorySize, GEMM_SMEM_BYTES);
    cudaFuncSetAttribute(gemm_mma<2>, cudaFuncAttributeMaxDynamicSharedMemorySize, GEMM_SMEM_BYTES);

    // weight prep (single merged launch)
    prep_weights_kernel<<<(PREP_TOTAL + 255) / 256, 256>>>(
        wq, wk, wv, w_proj, w1, w2, p_wqkvT, p_wprojT, p_w1T, p_w2T);

    // 1. h = ln1(x)
    layernorm_kernel<<<M_TOK / 8, 256>>>(x, ln1_g, ln1_b, p_h);

    // 2. qkv = h @ Wqkv
    gemm_mma<0><<<dim3(QKV_N / 256, M_TOK / 128), 256, GEMM_SMEM_BYTES>>>(
        p_h, p_wqkvT, p_qkv, nullptr, nullptr, M_TOK, QKV_N, C_);

    // 3. causal attention (tensor cores)
    attn_tc_kernel<<<dim3(B_ * H_, T_ / 64), 128>>>(p_qkv, p_att);

    // 4. xmid = x + att @ w_proj + b_proj
    gemm_mma<2><<<dim3(C_ / 256, M_TOK / 128), 256, GEMM_SMEM_BYTES>>>(
        p_att, p_wprojT, p_xmid, b_proj, x, M_TOK, C_, C_);

    // 5. h2 = ln2(xmid)
    layernorm_kernel<<<M_TOK / 8, 256>>>(p_xmid, ln2_g, ln2_b, p_h2);

    // 6. ffn = relu(h2 @ w1 + b1)
    gemm_mma<1><<<dim3(FF_ / 256, M_TOK / 128), 256, GEMM_SMEM_BYTES>>>(
        p_h2, p_w1T, p_ffn, b1, nullptr, M_TOK, FF_, C_);

    // 7. out = xmid + ffn @ w2 + b2
    gemm_mma<2><<<dim3(C_ / 256, M_TOK / 128), 256, GEMM_SMEM_BYTES>>>(
        p_ffn, p_w2T, out, b2, p_xmid, M_TOK, C_, FF_);
}

// round 8
// speedup vs baseline: 2.9752x; 1.1300x over previous
#include <cuda_runtime.h>
#include <cstdint>

// Problem constants
#define B_    16
#define T_    1024
#define C_    256
#define H_    8
#define D_    32
#define M_TOK (B_ * T_)      // 16384 tokens
#define FF_   (4 * C_)       // 1024
#define QKV_N (3 * C_)       // 768
#define ATT_SCALE 0.0625f
#define LN_EPS 1e-5f

// ---------------------------------------------------------------------------
// Scratch (device globals)
// ---------------------------------------------------------------------------
__device__ float g_h     [M_TOK * C_];
__device__ float g_qkv   [M_TOK * QKV_N];
__device__ float g_att   [M_TOK * C_];
__device__ float g_xmid  [M_TOK * C_];
__device__ float g_h2    [M_TOK * C_];
__device__ float g_ffn   [M_TOK * FF_];
__device__ float g_wqkvT [QKV_N * C_];   // [N=768][K=256], tf32-rounded
__device__ float g_wprojT[C_ * C_];      // tf32-rounded
__device__ float g_w1T   [FF_ * C_];     // tf32-rounded
__device__ float g_w2T   [C_ * FF_];     // tf32-rounded

// ---------------------------------------------------------------------------
// Small helpers
// ---------------------------------------------------------------------------
__device__ __forceinline__ float tf32_rn(float x) {
    float y;
    asm("cvt.rna.tf32.f32 %0, %1;" : "=f"(y) : "f"(x));
    return y;
}
__device__ __forceinline__ void mma_tf32(float* d,
                                         const uint32_t* a, const uint32_t* b,
                                         const float* c) {
    asm volatile(
        "mma.sync.aligned.m16n8k8.row.col.f32.tf32.tf32.f32 "
        "{%0,%1,%2,%3}, {%4,%5,%6,%7}, {%8,%9}, {%10,%11,%12,%13};"
        : "=f"(d[0]), "=f"(d[1]), "=f"(d[2]), "=f"(d[3])
        : "r"(a[0]), "r"(a[1]), "r"(a[2]), "r"(a[3]),
          "r"(b[0]), "r"(b[1]),
          "f"(c[0]), "f"(c[1]), "f"(c[2]), "f"(c[3]));
}
// swizzled column for element (row, k) in a [rows][32] tile
__device__ __forceinline__ int swz(int row, int k) {
    return k ^ (8 * (row & 3)) ^ (4 * ((row >> 2) & 1));
}
__device__ __forceinline__ void cp_async16(float* sp, const float* gp) {
    uint32_t sa = (uint32_t)__cvta_generic_to_shared(sp);
    asm volatile("cp.async.cg.shared.global [%0], [%1], 16;"
                 :: "r"(sa), "l"(gp) : "memory");
}
#define CP_COMMIT() asm volatile("cp.async.commit_group;" ::: "memory")
#define CP_WAIT1()  asm volatile("cp.async.wait_group 1;" ::: "memory")

// ---------------------------------------------------------------------------
// Weight prep (tf32-rounded outputs), single merged kernel
// ---------------------------------------------------------------------------
#define PREP_TOTAL (QKV_N * C_ + C_ * C_ + C_ * FF_ + FF_ * C_)

__global__ void prep_weights_kernel(
    const float* __restrict__ wq, const float* __restrict__ wk,
    const float* __restrict__ wv, const float* __restrict__ w_proj,
    const float* __restrict__ w1, const float* __restrict__ w2,
    float* __restrict__ wqkvT, float* __restrict__ wprojT,
    float* __restrict__ w1T, float* __restrict__ w2T) {
    int i = blockIdx.x * blockDim.x + threadIdx.x;
    if (i < QKV_N * C_) {
        int n = i / C_;
        int c = i % C_;
        const float* w = (n < C_) ? wq : ((n < 2 * C_) ? wk : wv);
        int nn = n & (C_ - 1);
        wqkvT[i] = tf32_rn(w[((size_t)(nn >> 5) * C_ + c) * D_ + (nn & 31)]);
        return;
    }
    i -= QKV_N * C_;
    if (i < C_ * C_) {
        int r = i / C_, c = i % C_;
        wprojT[c * C_ + r] = tf32_rn(w_proj[i]);
        return;
    }
    i -= C_ * C_;
    if (i < C_ * FF_) {
        int r = i / FF_, c = i % FF_;
        w1T[c * C_ + r] = tf32_rn(w1[i]);
        return;
    }
    i -= C_ * FF_;
    if (i < FF_ * C_) {
        int r = i / C_, c = i % C_;
        w2T[c * FF_ + r] = tf32_rn(w2[i]);
    }
}

// ---------------------------------------------------------------------------
// LayerNorm: one warp per 256-float row; OUTPUT tf32-rounded (GEMM input)
// ---------------------------------------------------------------------------
__global__ __launch_bounds__(256) void layernorm_kernel(
    const float* __restrict__ in, const float* __restrict__ g,
    const float* __restrict__ b, float* __restrict__ out) {
    int warp = threadIdx.x >> 5;
    int lane = threadIdx.x & 31;
    int row  = blockIdx.x * 8 + warp;

    const float4* rp = (const float4*)(in + (size_t)row * C_);
    float4 v0 = rp[lane];
    float4 v1 = rp[lane + 32];

    float s  = v0.x + v0.y + v0.z + v0.w + v1.x + v1.y + v1.z + v1.w;
    float ss = v0.x * v0.x + v0.y * v0.y + v0.z * v0.z + v0.w * v0.w
             + v1.x * v1.x + v1.y * v1.y + v1.z * v1.z + v1.w * v1.w;
#pragma unroll
    for (int off = 16; off; off >>= 1) {
        s  += __shfl_xor_sync(0xffffffffu, s,  off);
        ss += __shfl_xor_sync(0xffffffffu, ss, off);
    }
    float mean = s * (1.0f / C_);
    float var  = ss * (1.0f / C_) - mean * mean;
    float inv  = rsqrtf(var + LN_EPS);

    const float4* gp = (const float4*)g;
    const float4* bp = (const float4*)b;
    float4 g0 = gp[lane], g1 = gp[lane + 32];
    float4 b0 = bp[lane], b1 = bp[lane + 32];

    float4 o0, o1;
    o0.x = tf32_rn((v0.x - mean) * inv * g0.x + b0.x);
    o0.y = tf32_rn((v0.y - mean) * inv * g0.y + b0.y);
    o0.z = tf32_rn((v0.z - mean) * inv * g0.z + b0.z);
    o0.w = tf32_rn((v0.w - mean) * inv * g0.w + b0.w);
    o1.x = tf32_rn((v1.x - mean) * inv * g1.x + b1.x);
    o1.y = tf32_rn((v1.y - mean) * inv * g1.y + b1.y);
    o1.z = tf32_rn((v1.z - mean) * inv * g1.z + b1.z);
    o1.w = tf32_rn((v1.w - mean) * inv * g1.w + b1.w);

    float4* op = (float4*)(out + (size_t)row * C_);
    op[lane]      = o0;
    op[lane + 32] = o1;
}

// ---------------------------------------------------------------------------
// tf32 mma.sync GEMM with cp.async 2-stage pipeline.
// Inputs (A, Bt) are PRE-ROUNDED to tf32 by their producers.
// CTA tile 128x256, BK=32, 8 warps (2m x 4n), warp tile 64x64, XOR swizzle.
// EPI: 0 = plain, 1 = +bias+relu (tf32-rounded store), 2 = +bias+residual
// ---------------------------------------------------------------------------
#define GA_SZ (128 * 32)
#define GB_SZ (256 * 32)
#define GEMM_SMEM_BYTES (2 * (GA_SZ + GB_SZ) * 4)   // 98304

template <int EPI>
__global__ __launch_bounds__(256, 1) void gemm_mma(
    const float* __restrict__ A, const float* __restrict__ Bt,
    float* __restrict__ Cm, const float* __restrict__ bias,
    const float* __restrict__ res, int M, int N, int K) {
    extern __shared__ float dynsm[];
    float* const Abuf[2] = { dynsm, dynsm + GA_SZ };
    float* const Bbuf[2] = { dynsm + 2 * GA_SZ, dynsm + 2 * GA_SZ + GB_SZ };

    const int tid  = threadIdx.x;
    const int wid  = tid >> 5;
    const int lane = tid & 31;
    const int wm   = (wid & 1) * 64;
    const int wn   = (wid >> 1) * 64;
    const int gq   = lane >> 2;
    const int tq   = lane & 3;
    const int brow = blockIdx.y * 128;
    const int bcol = blockIdx.x * 256;

    float acc[4][8][4];
#pragma unroll
    for (int i = 0; i < 4; i++)
#pragma unroll
        for (int j = 0; j < 8; j++)
#pragma unroll
            for (int q = 0; q < 4; q++) acc[i][j][q] = 0.0f;

    const float* Ag = A + (size_t)brow * K;
    const float* Bg = Bt + (size_t)bcol * K;
    const int KC = K >> 5;

    // per-thread copy geometry
    const int cr = tid >> 3;          // 0..31 (A rows 0..127 via +i*32; B likewise)
    const int cc = (tid & 7) * 4;     // k offset 0..28

    // issue one 32-k chunk into stage s
    auto issue = [&](int kc, int s) {
        const float* Agn = Ag + kc * 32 + cc;
        const float* Bgn = Bg + kc * 32 + cc;
        float* As = Abuf[s];
        float* Bs = Bbuf[s];
#pragma unroll
        for (int i = 0; i < 4; i++) {
            int r = cr + i * 32;
            cp_async16(&As[r * 32 + swz(r, cc)], Agn + (size_t)r * K);
        }
#pragma unroll
        for (int i = 0; i < 8; i++) {
            int r = cr + i * 32;
            cp_async16(&Bs[r * 32 + swz(r, cc)], Bgn + (size_t)r * K);
        }
    };

    issue(0, 0); CP_COMMIT();
    if (KC > 1) issue(1, 1);
    CP_COMMIT();

    for (int kc = 0; kc < KC; kc++) {
        CP_WAIT1();          // chunk kc landed
        __syncthreads();

        float* As = Abuf[kc & 1];
        float* Bs = Bbuf[kc & 1];

#pragma unroll
        for (int ks = 0; ks < 4; ks++) {
            const int colA  = (ks * 8 + tq) ^ (8 * (gq & 3)) ^ (4 * ((gq >> 2) & 1));
            const int colA4 = colA ^ 4;

            uint32_t afr[4][4];
#pragma unroll
            for (int mt = 0; mt < 4; mt++) {
                int m0 = wm + mt * 16;
                afr[mt][0] = __float_as_uint(As[(m0 + gq    ) * 32 + colA ]);
                afr[mt][1] = __float_as_uint(As[(m0 + gq + 8) * 32 + colA ]);
                afr[mt][2] = __float_as_uint(As[(m0 + gq    ) * 32 + colA4]);
                afr[mt][3] = __float_as_uint(As[(m0 + gq + 8) * 32 + colA4]);
            }
            uint32_t bfr[8][2];
#pragma unroll
            for (int nt = 0; nt < 8; nt++) {
                int n0 = wn + nt * 8;
                bfr[nt][0] = __float_as_uint(Bs[(n0 + gq) * 32 + colA ]);
                bfr[nt][1] = __float_as_uint(Bs[(n0 + gq) * 32 + colA4]);
            }
#pragma unroll
            for (int mt = 0; mt < 4; mt++)
#pragma unroll
                for (int nt = 0; nt < 8; nt++)
                    mma_tf32(acc[mt][nt], afr[mt], bfr[nt], acc[mt][nt]);
        }
        __syncthreads();     // all readers done with this stage
        if (kc + 2 < KC) issue(kc + 2, kc & 1);
        CP_COMMIT();         // always commit to keep group accounting simple
    }

    // epilogue
#pragma unroll
    for (int mt = 0; mt < 4; mt++) {
        int row0 = brow + wm + mt * 16 + gq;
#pragma unroll
        for (int half = 0; half < 2; half++) {
            int row = row0 + half * 8;
            float* outr = Cm + (size_t)row * N;
            const float* resr = (EPI == 2) ? (res + (size_t)row * N) : nullptr;
#pragma unroll
            for (int nt = 0; nt < 8; nt++) {
                int col = bcol + wn + nt * 8 + tq * 2;
                float2 v;
                v.x = acc[mt][nt][half * 2 + 0];
                v.y = acc[mt][nt][half * 2 + 1];
                if (EPI != 0) {
                    v.x += bias[col + 0];
                    v.y += bias[col + 1];
                }
                if (EPI == 1) {          // relu + tf32 round (feeds next GEMM)
                    v.x = tf32_rn(fmaxf(v.x, 0.0f));
                    v.y = tf32_rn(fmaxf(v.y, 0.0f));
                }
                if (EPI == 2) {
                    float2 rr = *(const float2*)(resr + col);
                    v.x += rr.x;
                    v.y += rr.y;
                }
                *(float2*)(outr + col) = v;
            }
        }
    }
}

// ---------------------------------------------------------------------------
// Tensor-core causal flash attention (tf32 mma.sync).
// Conflict-free smem strides: Q/K=36, V=40, P=68. Float4 tile stores.
// Ps aliases Qs region (Qs dead after fragment read; barrier separates).
// smem pool = 55 KB -> 4 CTAs/SM.
// Output tf32-rounded (feeds proj GEMM).
// ---------------------------------------------------------------------------
#define PS_FLOATS (4 * 16 * 68)                 // 4352 (>= Qs 64*36 = 2304)
#define KS_OFF    PS_FLOATS                     // 4352
#define VS_OFF    (KS_OFF + 2 * 64 * 36)        // 8960
#define POOL_SZ   (VS_OFF + 2 * 64 * 40)        // 14080 floats = 56320 B

__global__ __launch_bounds__(128) void attn_tc_kernel(
    const float* __restrict__ qkv, float* __restrict__ att) {
    __shared__ float pool[POOL_SZ];
    float* const Qs = pool;                                  // [64][36]
    float* const Ps = pool;                                  // [4][16][68]
    float* const Ks0 = pool + KS_OFF;                        // [2][64][36]
    float* const Vs0 = pool + VS_OFF;                        // [2][64][40]

    const int bh = blockIdx.x;
    const int b  = bh >> 3;
    const int h  = bh & 7;
    const int qt = blockIdx.y;
    const int tid  = threadIdx.x;
    const int wid  = tid >> 5;
    const int lane = tid & 31;
    const int gq   = lane >> 2;
    const int tq   = lane & 3;
    const size_t tokbase = (size_t)b * T_;
    const int qrow0 = qt * 64;
    const int m0 = wid * 16;

    // load + scale + round Q tile (64x32), float4 stores, stride 36
#pragma unroll
    for (int i = 0; i < 4; i++) {
        int e = tid + i * 128;
        int r = e >> 3, c4 = e & 7;
        float4 v = *(const float4*)(qkv + (tokbase + qrow0 + r) * QKV_N + h * D_ + c4 * 4);
        v.x = tf32_rn(v.x * ATT_SCALE);
        v.y = tf32_rn(v.y * ATT_SCALE);
        v.z = tf32_rn(v.z * ATT_SCALE);
        v.w = tf32_rn(v.w * ATT_SCALE);
        *(float4*)&Qs[r * 36 + c4 * 4] = v;
    }

    // prefetch K/V tile 0 into registers
    float4 rk[4], rv[4];
#pragma unroll
    for (int i = 0; i < 4; i++) {
        int e = tid + i * 128;
        int r = e >> 3, c4 = e & 7;
        const float* base = qkv + (tokbase + r) * QKV_N + h * D_ + c4 * 4;
        rk[i] = *(const float4*)(base + C_);
        rv[i] = *(const float4*)(base + 2 * C_);
    }
    __syncthreads();

    uint32_t qf[4][4];
#pragma unroll
    for (int ks = 0; ks < 4; ks++) {
        qf[ks][0] = __float_as_uint(Qs[(m0 + gq    ) * 36 + 8 * ks + tq    ]);
        qf[ks][1] = __float_as_uint(Qs[(m0 + gq + 8) * 36 + 8 * ks + tq    ]);
        qf[ks][2] = __float_as_uint(Qs[(m0 + gq    ) * 36 + 8 * ks + tq + 4]);
        qf[ks][3] = __float_as_uint(Qs[(m0 + gq + 8) * 36 + 8 * ks + tq + 4]);
    }

    const int r0 = qrow0 + m0 + gq;
    const int r1 = r0 + 8;

    float mrow0 = -1e30f, mrow1 = -1e30f;
    float l0 = 0.0f, l1 = 0.0f;
    float o[4][4];
#pragma unroll
    for (int i = 0; i < 4; i++)
#pragma unroll
        for (int j = 0; j < 4; j++) o[i][j] = 0.0f;

    float* const Pw = Ps + wid * 16 * 68;

    for (int s0 = 0; s0 <= qrow0; s0 += 64) {
        const int buf = (s0 >> 6) & 1;
        float* const Ks = Ks0 + buf * 64 * 36;
        float* const Vs = Vs0 + buf * 64 * 40;

        // store prefetched tile (tf32-rounded), float4
#pragma unroll
        for (int i = 0; i < 4; i++) {
            int e = tid + i * 128;
            int r = e >> 3, c4 = e & 7;
            float4 kv, vv;
            kv.x = tf32_rn(rk[i].x); kv.y = tf32_rn(rk[i].y);
            kv.z = tf32_rn(rk[i].z); kv.w = tf32_rn(rk[i].w);
            vv.x = tf32_rn(rv[i].x); vv.y = tf32_rn(rv[i].y);
            vv.z = tf32_rn(rv[i].z); vv.w = tf32_rn(rv[i].w);
            *(float4*)&Ks[r * 36 + c4 * 4] = kv;
            *(float4*)&Vs[r * 40 + c4 * 4] = vv;
        }
        __syncthreads();

        // prefetch next tile (hidden under compute)
        if (s0 + 64 <= qrow0) {
#pragma unroll
            for (int i = 0; i < 4; i++) {
                int e = tid + i * 128;
                int r = e >> 3, c4 = e & 7;
                const float* base = qkv + (tokbase + s0 + 64 + r) * QKV_N + h * D_ + c4 * 4;
                rk[i] = *(const float4*)(base + C_);
                rv[i] = *(const float4*)(base + 2 * C_);
            }
        }

        // --- S = Q @ K^T ---
        float S[8][4];
#pragma unroll
        for (int nt = 0; nt < 8; nt++) {
            S[nt][0] = S[nt][1] = S[nt][2] = S[nt][3] = 0.0f;
#pragma unroll
            for (int ks = 0; ks < 4; ks++) {
                uint32_t bfr[2];
                bfr[0] = __float_as_uint(Ks[(nt * 8 + gq) * 36 + 8 * ks + tq    ]);
                bfr[1] = __float_as_uint(Ks[(nt * 8 + gq) * 36 + 8 * ks + tq + 4]);
                mma_tf32(S[nt], qf[ks], bfr, S[nt]);
            }
        }

        // causal mask (diagonal tile only)
        if (s0 == qrow0) {
#pragma unroll
            for (int nt = 0; nt < 8; nt++) {
                int col = s0 + nt * 8 + 2 * tq;
                if (col     > r0) S[nt][0] = -1e30f;
                if (col + 1 > r0) S[nt][1] = -1e30f;
                if (col     > r1) S[nt][2] = -1e30f;
                if (col + 1 > r1) S[nt][3] = -1e30f;
            }
        }

        // online softmax
        float mx0 = -1e30f, mx1 = -1e30f;
#pragma unroll
        for (int nt = 0; nt < 8; nt++) {
            mx0 = fmaxf(mx0, fmaxf(S[nt][0], S[nt][1]));
            mx1 = fmaxf(mx1, fmaxf(S[nt][2], S[nt][3]));
        }
        mx0 = fmaxf(mx0, __shfl_xor_sync(0xffffffffu, mx0, 1));
        mx0 = fmaxf(mx0, __shfl_xor_sync(0xffffffffu, mx0, 2));
        mx1 = fmaxf(mx1, __shfl_xor_sync(0xffffffffu, mx1, 1));
        mx1 = fmaxf(mx1, __shfl_xor_sync(0xffffffffu, mx1, 2));

        float mn0 = fmaxf(mrow0, mx0);
        float mn1 = fmaxf(mrow1, mx1);
        float a0 = __expf(mrow0 - mn0);
        float a1 = __expf(mrow1 - mn1);
        mrow0 = mn0;
        mrow1 = mn1;

        float sum0 = 0.0f, sum1 = 0.0f;
#pragma unroll
        for (int nt = 0; nt < 8; nt++) {
            S[nt][0] = __expf(S[nt][0] - mn0);
            S[nt][1] = __expf(S[nt][1] - mn0);
            S[nt][2] = __expf(S[nt][2] - mn1);
            S[nt][3] = __expf(S[nt][3] - mn1);
            sum0 += S[nt][0] + S[nt][1];
            sum1 += S[nt][2] + S[nt][3];
        }
        sum0 += __shfl_xor_sync(0xffffffffu, sum0, 1);
        sum0 += __shfl_xor_sync(0xffffffffu, sum0, 2);
        sum1 += __shfl_xor_sync(0xffffffffu, sum1, 1);
        sum1 += __shfl_xor_sync(0xffffffffu, sum1, 2);
        l0 = l0 * a0 + sum0;
        l1 = l1 * a1 + sum1;

#pragma unroll
        for (int d4 = 0; d4 < 4; d4++) {
            o[d4][0] *= a0;
            o[d4][1] *= a0;
            o[d4][2] *= a1;
            o[d4][3] *= a1;
        }

        // stage P (tf32) to per-warp smem, stride 68
#pragma unroll
        for (int nt = 0; nt < 8; nt++) {
            float2 p0 = make_float2(tf32_rn(S[nt][0]), tf32_rn(S[nt][1]));
            float2 p1 = make_float2(tf32_rn(S[nt][2]), tf32_rn(S[nt][3]));
            *(float2*)&Pw[(gq    ) * 68 + nt * 8 + 2 * tq] = p0;
            *(float2*)&Pw[(gq + 8) * 68 + nt * 8 + 2 * tq] = p1;
        }
        __syncwarp();

        // O += P @ V
#pragma unroll
        for (int ks = 0; ks < 8; ks++) {
            uint32_t pf[4];
            pf[0] = __float_as_uint(Pw[(gq    ) * 68 + 8 * ks + tq    ]);
            pf[1] = __float_as_uint(Pw[(gq + 8) * 68 + 8 * ks + tq    ]);
            pf[2] = __float_as_uint(Pw[(gq    ) * 68 + 8 * ks + tq + 4]);
            pf[3] = __float_as_uint(Pw[(gq + 8) * 68 + 8 * ks + tq + 4]);
#pragma unroll
            for (int d4 = 0; d4 < 4; d4++) {
                uint32_t bfr[2];
                bfr[0] = __float_as_uint(Vs[(8 * ks + tq    ) * 40 + d4 * 8 + gq]);
                bfr[1] = __float_as_uint(Vs[(8 * ks + tq + 4) * 40 + d4 * 8 + gq]);
                mma_tf32(o[d4], pf, bfr, o[d4]);
            }
        }
        __syncwarp();
    }

    // write output, tf32-rounded (feeds proj GEMM)
    float inv0 = 1.0f / l0;
    float inv1 = 1.0f / l1;
#pragma unroll
    for (int d4 = 0; d4 < 4; d4++) {
        int col = h * D_ + d4 * 8 + 2 * tq;
        *(float2*)(att + (tokbase + r0) * C_ + col) =
            make_float2(tf32_rn(o[d4][0] * inv0), tf32_rn(o[d4][1] * inv0));
        *(float2*)(att + (tokbase + r1) * C_ + col) =
            make_float2(tf32_rn(o[d4][2] * inv1), tf32_rn(o[d4][3] * inv1));
    }
}

// ---------------------------------------------------------------------------
// Launch
// ---------------------------------------------------------------------------
extern "C" void kernel_launch(void* const* d_in, const int* in_sizes, int n_in,
                              void* d_out, int out_size) {
    const float* x      = (const float*)d_in[0];
    const float* wq     = (const float*)d_in[1];
    const float* wk     = (const float*)d_in[2];
    const float* wv     = (const float*)d_in[3];
    const float* w_proj = (const float*)d_in[4];
    const float* b_proj = (const float*)d_in[5];
    const float* w1     = (const float*)d_in[6];
    const float* b1     = (const float*)d_in[7];
    const float* w2     = (const float*)d_in[8];
    const float* b2     = (const float*)d_in[9];
    const float* ln1_g  = (const float*)d_in[10];
    const float* ln1_b  = (const float*)d_in[11];
    const float* ln2_g  = (const float*)d_in[12];
    const float* ln2_b  = (const float*)d_in[13];
    float* out = (float*)d_out;

    float *p_h, *p_qkv, *p_att, *p_xmid, *p_h2, *p_ffn;
    float *p_wqkvT, *p_wprojT, *p_w1T, *p_w2T;
    cudaGetSymbolAddress((void**)&p_h,      g_h);
    cudaGetSymbolAddress((void**)&p_qkv,    g_qkv);
    cudaGetSymbolAddress((void**)&p_att,    g_att);
    cudaGetSymbolAddress((void**)&p_xmid,   g_xmid);
    cudaGetSymbolAddress((void**)&p_h2,     g_h2);
    cudaGetSymbolAddress((void**)&p_ffn,    g_ffn);
    cudaGetSymbolAddress((void**)&p_wqkvT,  g_wqkvT);
    cudaGetSymbolAddress((void**)&p_wprojT, g_wprojT);
    cudaGetSymbolAddress((void**)&p_w1T,    g_w1T);
    cudaGetSymbolAddress((void**)&p_w2T,    g_w2T);

    cudaFuncSetAttribute(gemm_mma<0>, cudaFuncAttributeMaxDynamicSharedMemorySize, GEMM_SMEM_BYTES);
    cudaFuncSetAttribute(gemm_mma<1>, cudaFuncAttributeMaxDynamicSharedMemorySize, GEMM_SMEM_BYTES);
    cudaFuncSetAttribute(gemm_mma<2>, cudaFuncAttributeMaxDynamicSharedMemorySize, GEMM_SMEM_BYTES);

    // weight prep (single merged launch, tf32-rounded)
    prep_weights_kernel<<<(PREP_TOTAL + 255) / 256, 256>>>(
        wq, wk, wv, w_proj, w1, w2, p_wqkvT, p_wprojT, p_w1T, p_w2T);

    // 1. h = ln1(x)                       (tf32-rounded output)
    layernorm_kernel<<<M_TOK / 8, 256>>>(x, ln1_g, ln1_b, p_h);

    // 2. qkv = h @ Wqkv
    gemm_mma<0><<<dim3(QKV_N / 256, M_TOK / 128), 256, GEMM_SMEM_BYTES>>>(
        p_h, p_wqkvT, p_qkv, nullptr, nullptr, M_TOK, QKV_N, C_);

    // 3. causal attention                 (tf32-rounded output)
    attn_tc_kernel<<<dim3(B_ * H_, T_ / 64), 128>>>(p_qkv, p_att);

    // 4. xmid = x + att @ w_proj + b_proj
    gemm_mma<2><<<dim3(C_ / 256, M_TOK / 128), 256, GEMM_SMEM_BYTES>>>(
        p_att, p_wprojT, p_xmid, b_proj, x, M_TOK, C_, C_);

    // 5. h2 = ln2(xmid)                   (tf32-rounded output)
    layernorm_kernel<<<M_TOK / 8, 256>>>(p_xmid, ln2_g, ln2_b, p_h2);

    // 6. ffn = relu(h2 @ w1 + b1)         (tf32-rounded output)
    gemm_mma<1><<<dim3(FF_ / 256, M_TOK / 128), 256, GEMM_SMEM_BYTES>>>(
        p_h2, p_w1T, p_ffn, b1, nullptr, M_TOK, FF_, C_);

    // 7. out = xmid + ffn @ w2 + b2
    gemm_mma<2><<<dim3(C_ / 256, M_TOK / 128), 256, GEMM_SMEM_BYTES>>>(
        p_ffn, p_w2T, out, b2, p_xmid, M_TOK, C_, FF_);
}